// round 2
// baseline (speedup 1.0000x reference)
#include <cuda_runtime.h>

#define N_NODES 100000
#define N_EDGES 1600000
#define HID 128
#define NH4 (HID/4)
#define N_GRAPHS 512
#define N_CLASSES 64
#define BN_EPS 1e-5f

// ---------------- scratch (device globals; allocation-free) ----------------
__device__ float g_hW[N_NODES * HID];   // h @ W for current layer
__device__ float g_z [N_NODES * HID];   // pre-BN conv output
__device__ float g_hA[N_NODES * HID];   // layer activations ping
__device__ float g_hB[N_NODES * HID];   // layer activations pong
__device__ float g_dinv[N_NODES];
__device__ int   g_cnt[N_NODES];        // in-degree (without self loop)
__device__ int   g_rowptr[N_NODES + 1];
__device__ int   g_cursor[N_NODES];
__device__ int   g_esrc[N_EDGES];       // CSR-sorted source node per edge
__device__ float g_ecoef[N_EDGES];      // dinv[src]*dinv[dst] per sorted edge
__device__ float g_stats[3 * 2 * HID];  // per layer: sum[128], sumsq[128]
__device__ float g_scale[HID];
__device__ float g_shift[HID];
__device__ float g_psum[N_GRAPHS * HID];
__device__ unsigned g_pmax[N_GRAPHS * HID];
__device__ int   g_pcnt[N_GRAPHS];

// ---------------- kernels ----------------

__global__ __launch_bounds__(256) void zero_kernel() {
    int i = blockIdx.x * blockDim.x + threadIdx.x;
    int stride = gridDim.x * blockDim.x;
    for (int j = i; j < N_NODES; j += stride) { g_cnt[j] = 0; g_cursor[j] = 0; }
    for (int j = i; j < 3 * 2 * HID; j += stride) g_stats[j] = 0.0f;
    for (int j = i; j < N_GRAPHS * HID; j += stride) { g_psum[j] = 0.0f; g_pmax[j] = 0u; }
    for (int j = i; j < N_GRAPHS; j += stride) g_pcnt[j] = 0;
}

__global__ __launch_bounds__(256) void hist_kernel(const int* __restrict__ dst) {
    int e = blockIdx.x * blockDim.x + threadIdx.x;
    if (e < N_EDGES) atomicAdd(&g_cnt[dst[e]], 1);
}

__global__ __launch_bounds__(256) void dinv_kernel() {
    int i = blockIdx.x * blockDim.x + threadIdx.x;
    if (i < N_NODES) g_dinv[i] = rsqrtf((float)g_cnt[i] + 1.0f);
}

// single-block exclusive scan of g_cnt -> g_rowptr
__global__ __launch_bounds__(1024) void scan_kernel() {
    __shared__ int sh[1024];
    const int T = 1024;
    const int CH = (N_NODES + T - 1) / T;  // 98
    int t = threadIdx.x;
    int base = t * CH;
    int s = 0;
    #pragma unroll 1
    for (int j = 0; j < CH; ++j) {
        int idx = base + j;
        if (idx < N_NODES) s += g_cnt[idx];
    }
    sh[t] = s;
    __syncthreads();
    // inclusive Hillis-Steele
    for (int off = 1; off < T; off <<= 1) {
        int v = (t >= off) ? sh[t - off] : 0;
        __syncthreads();
        sh[t] += v;
        __syncthreads();
    }
    int run = sh[t] - s;  // exclusive prefix for this chunk
    #pragma unroll 1
    for (int j = 0; j < CH; ++j) {
        int idx = base + j;
        if (idx < N_NODES) { g_rowptr[idx] = run; run += g_cnt[idx]; }
    }
    if (t == T - 1) g_rowptr[N_NODES] = sh[T - 1];
}

__global__ __launch_bounds__(256) void scatter_kernel(const int* __restrict__ src,
                                                      const int* __restrict__ dst) {
    int e = blockIdx.x * blockDim.x + threadIdx.x;
    if (e >= N_EDGES) return;
    int d = dst[e], s = src[e];
    int pos = g_rowptr[d] + atomicAdd(&g_cursor[d], 1);
    g_esrc[pos] = s;
    g_ecoef[pos] = g_dinv[s] * g_dinv[d];
}

// C[M,128] = A[M,128] @ W[128,128]; A selected by sel (0 = external, 1 = g_hA, 2 = g_hB)
__global__ __launch_bounds__(256) void gemm_kernel(const float* __restrict__ Aext, int sel,
                                                   const float* __restrict__ W) {
    const float* A = (sel == 0) ? Aext : (sel == 1 ? g_hA : g_hB);
    __shared__ float As[64 * 16];
    __shared__ float Ws[16 * 128];
    const int M = N_NODES;
    int tid = threadIdx.x;          // 256
    int tx = tid & 31;              // 32 col groups (4 cols each)
    int ty = tid >> 5;              // 8 row groups (8 rows each, stride 8)
    int rowBase = blockIdx.x * 64;

    float acc[8][4];
#pragma unroll
    for (int i = 0; i < 8; ++i)
#pragma unroll
        for (int j = 0; j < 4; ++j) acc[i][j] = 0.0f;

    for (int kt = 0; kt < 128; kt += 16) {
        // load A tile 64x16
        {
            int lin = tid * 4;
            int r = lin >> 4, k = lin & 15;
            int row = rowBase + r;
            float4 v = make_float4(0, 0, 0, 0);
            if (row < M) v = *(const float4*)&A[row * 128 + kt + k];
            *(float4*)&As[lin] = v;
        }
        // load W tile 16x128
        {
            int lin = tid * 8;
            int k = lin >> 7, c = lin & 127;
            *(float4*)&Ws[lin]     = *(const float4*)&W[(kt + k) * 128 + c];
            *(float4*)&Ws[lin + 4] = *(const float4*)&W[(kt + k) * 128 + c + 4];
        }
        __syncthreads();
#pragma unroll
        for (int kk = 0; kk < 16; ++kk) {
            float4 wv = *(float4*)&Ws[kk * 128 + tx * 4];
#pragma unroll
            for (int i = 0; i < 8; ++i) {
                float a = As[(ty + 8 * i) * 16 + kk];
                acc[i][0] += a * wv.x;
                acc[i][1] += a * wv.y;
                acc[i][2] += a * wv.z;
                acc[i][3] += a * wv.w;
            }
        }
        __syncthreads();
    }
#pragma unroll
    for (int i = 0; i < 8; ++i) {
        int row = rowBase + ty + 8 * i;
        if (row < M) {
            float4 v = make_float4(acc[i][0], acc[i][1], acc[i][2], acc[i][3]);
            *(float4*)&g_hW[row * 128 + tx * 4] = v;
        }
    }
}

// warp per node: z[i] = sum_e coef*hW[src] + dinv[i]^2 * hW[i] + b
__global__ __launch_bounds__(256) void agg_kernel(const float* __restrict__ b) {
    int warp = (blockIdx.x * blockDim.x + threadIdx.x) >> 5;
    if (warp >= N_NODES) return;
    int lane = threadIdx.x & 31;
    const float4* hw4 = (const float4*)g_hW;
    float4 acc = make_float4(0, 0, 0, 0);
    int e0 = g_rowptr[warp], e1 = g_rowptr[warp + 1];
    for (int e = e0; e < e1; ++e) {
        int s = g_esrc[e];
        float c = g_ecoef[e];
        float4 v = hw4[s * NH4 + lane];
        acc.x += c * v.x; acc.y += c * v.y; acc.z += c * v.z; acc.w += c * v.w;
    }
    float di = g_dinv[warp];
    float d2 = di * di;
    float4 v = hw4[warp * NH4 + lane];
    acc.x += d2 * v.x; acc.y += d2 * v.y; acc.z += d2 * v.z; acc.w += d2 * v.w;
    float4 bb = ((const float4*)b)[lane];
    acc.x += bb.x; acc.y += bb.y; acc.z += bb.z; acc.w += bb.w;
    ((float4*)g_z)[warp * NH4 + lane] = acc;
}

// column sums / sumsq of g_z -> g_stats[layer]
__global__ __launch_bounds__(128) void stats_kernel(int layer) {
    int c = threadIdx.x;  // 128
    int chunk = (N_NODES + gridDim.x - 1) / gridDim.x;
    int n0 = blockIdx.x * chunk;
    int n1 = min(n0 + chunk, N_NODES);
    float s = 0.0f, q = 0.0f;
    for (int n = n0; n < n1; ++n) {
        float v = g_z[n * HID + c];
        s += v; q += v * v;
    }
    float* st = &g_stats[layer * 2 * HID];
    atomicAdd(&st[c], s);
    atomicAdd(&st[HID + c], q);
}

__global__ __launch_bounds__(128) void bnprep_kernel(const float* __restrict__ gam,
                                                     const float* __restrict__ bet, int layer) {
    int c = threadIdx.x;  // 128
    const float* st = &g_stats[layer * 2 * HID];
    const float invN = 1.0f / (float)N_NODES;
    float mu = st[c] * invN;
    float var = st[HID + c] * invN - mu * mu;
    float sc = gam[c] * rsqrtf(var + BN_EPS);
    g_scale[c] = sc;
    g_shift[c] = bet[c] - mu * sc;
}

// y = relu(z*scale + shift (+ residual)); residSel/outSel: 1=g_hA 2=g_hB 0=none
__global__ __launch_bounds__(256) void bn_kernel(int residSel, int outSel) {
    float* out = (outSel == 1) ? g_hA : g_hB;
    const float* res = (residSel == 1) ? g_hA : (residSel == 2 ? g_hB : nullptr);
    int i = blockIdx.x * blockDim.x + threadIdx.x;
    const int total = N_NODES * NH4;
    if (i >= total) return;
    int c4 = (i & (NH4 - 1)) * 4;
    float4 z = ((const float4*)g_z)[i];
    float4 y;
    y.x = z.x * g_scale[c4 + 0] + g_shift[c4 + 0];
    y.y = z.y * g_scale[c4 + 1] + g_shift[c4 + 1];
    y.z = z.z * g_scale[c4 + 2] + g_shift[c4 + 2];
    y.w = z.w * g_scale[c4 + 3] + g_shift[c4 + 3];
    if (res) {
        float4 r = ((const float4*)res)[i];
        y.x += r.x; y.y += r.y; y.z += r.z; y.w += r.w;
    }
    y.x = fmaxf(y.x, 0.0f); y.y = fmaxf(y.y, 0.0f);
    y.z = fmaxf(y.z, 0.0f); y.w = fmaxf(y.w, 0.0f);
    ((float4*)out)[i] = y;
}

__device__ __forceinline__ void pool_flush(int g, int lane, float4 s, float4 m, int cnt) {
    int base = g * HID + lane * 4;
    atomicAdd(&g_psum[base + 0], s.x);
    atomicAdd(&g_psum[base + 1], s.y);
    atomicAdd(&g_psum[base + 2], s.z);
    atomicAdd(&g_psum[base + 3], s.w);
    atomicMax(&g_pmax[base + 0], __float_as_uint(m.x));
    atomicMax(&g_pmax[base + 1], __float_as_uint(m.y));
    atomicMax(&g_pmax[base + 2], __float_as_uint(m.z));
    atomicMax(&g_pmax[base + 3], __float_as_uint(m.w));
    if (lane == 0) atomicAdd(&g_pcnt[g], cnt);
}

// warp handles 16 consecutive nodes (batch is sorted -> few flushes)
__global__ __launch_bounds__(256) void pool_kernel(const int* __restrict__ batch) {
    const int NPW = 16;
    int warp = (blockIdx.x * blockDim.x + threadIdx.x) >> 5;
    int lane = threadIdx.x & 31;
    int n0 = warp * NPW;
    if (n0 >= N_NODES) return;
    int n1 = min(n0 + NPW, N_NODES);
    const float4* h4 = (const float4*)g_hA;  // final activations live in g_hA
    float4 sacc = make_float4(0, 0, 0, 0);
    float4 macc = make_float4(0, 0, 0, 0);
    int cur = batch[n0];
    int cnt = 0;
    for (int n = n0; n < n1; ++n) {
        int g = batch[n];
        if (g != cur) {
            pool_flush(cur, lane, sacc, macc, cnt);
            sacc = make_float4(0, 0, 0, 0);
            macc = make_float4(0, 0, 0, 0);
            cnt = 0; cur = g;
        }
        float4 v = h4[n * NH4 + lane];
        sacc.x += v.x; sacc.y += v.y; sacc.z += v.z; sacc.w += v.w;
        macc.x = fmaxf(macc.x, v.x); macc.y = fmaxf(macc.y, v.y);
        macc.z = fmaxf(macc.z, v.z); macc.w = fmaxf(macc.w, v.w);
        ++cnt;
    }
    pool_flush(cur, lane, sacc, macc, cnt);
}

__global__ __launch_bounds__(64) void head_kernel(const float* __restrict__ Wh,
                                                  const float* __restrict__ bh,
                                                  float* __restrict__ out) {
    int g = blockIdx.x;   // 512
    int c = threadIdx.x;  // 64
    float cntf = (float)g_pcnt[g];
    float inv = 1.0f / fmaxf(cntf, 1.0f);
    float acc = bh[c];
    for (int k = 0; k < HID; ++k) {
        float s = g_psum[g * HID + k];
        float m = s * inv;
        float mx = __uint_as_float(g_pmax[g * HID + k]);
        acc += m * Wh[k * N_CLASSES + c]
             + s * Wh[(HID + k) * N_CLASSES + c]
             + mx * Wh[(2 * HID + k) * N_CLASSES + c];
    }
    out[g * N_CLASSES + c] = acc;
}

// ---------------- launch ----------------
extern "C" void kernel_launch(void* const* d_in, const int* in_sizes, int n_in,
                              void* d_out, int out_size) {
    const float* x    = (const float*)d_in[0];
    const int*   ei   = (const int*)d_in[1];
    const int*   src  = ei;
    const int*   dst  = ei + N_EDGES;
    const int*   batch = (const int*)d_in[2];
    const float* W1 = (const float*)d_in[3];
    const float* b1 = (const float*)d_in[4];
    const float* g1 = (const float*)d_in[5];
    const float* be1 = (const float*)d_in[6];
    const float* W2 = (const float*)d_in[7];
    const float* b2 = (const float*)d_in[8];
    const float* g2 = (const float*)d_in[9];
    const float* be2 = (const float*)d_in[10];
    const float* W3 = (const float*)d_in[11];
    const float* b3 = (const float*)d_in[12];
    const float* g3 = (const float*)d_in[13];
    const float* be3 = (const float*)d_in[14];
    const float* Wh = (const float*)d_in[15];
    const float* bh = (const float*)d_in[16];
    float* out = (float*)d_out;

    const int TB = 256;
    const int edgeBlocks = (N_EDGES + TB - 1) / TB;
    const int nodeBlocks = (N_NODES + TB - 1) / TB;
    const int gemmBlocks = (N_NODES + 63) / 64;
    const int aggBlocks = (N_NODES * 32 + TB - 1) / TB;   // warp per node
    const int bnBlocks = (N_NODES * NH4 + TB - 1) / TB;
    const int poolWarps = (N_NODES + 15) / 16;
    const int poolBlocks = (poolWarps * 32 + TB - 1) / TB;

    zero_kernel<<<256, TB>>>();
    hist_kernel<<<edgeBlocks, TB>>>(dst);
    dinv_kernel<<<nodeBlocks, TB>>>();
    scan_kernel<<<1, 1024>>>();
    scatter_kernel<<<edgeBlocks, TB>>>(src, dst);

    // ---- layer 1: x -> g_hA ----
    gemm_kernel<<<gemmBlocks, TB>>>(x, 0, W1);
    agg_kernel<<<aggBlocks, TB>>>(b1);
    stats_kernel<<<256, 128>>>(0);
    bnprep_kernel<<<1, 128>>>(g1, be1, 0);
    bn_kernel<<<bnBlocks, TB>>>(0, 1);

    // ---- layer 2: g_hA -> g_hB (residual g_hA) ----
    gemm_kernel<<<gemmBlocks, TB>>>(nullptr, 1, W2);
    agg_kernel<<<aggBlocks, TB>>>(b2);
    stats_kernel<<<256, 128>>>(1);
    bnprep_kernel<<<1, 128>>>(g2, be2, 1);
    bn_kernel<<<bnBlocks, TB>>>(1, 2);

    // ---- layer 3: g_hB -> g_hA (residual g_hB) ----
    gemm_kernel<<<gemmBlocks, TB>>>(nullptr, 2, W3);
    agg_kernel<<<aggBlocks, TB>>>(b3);
    stats_kernel<<<256, 128>>>(2);
    bnprep_kernel<<<1, 128>>>(g3, be3, 2);
    bn_kernel<<<bnBlocks, TB>>>(2, 1);

    // ---- pooling + head ----
    pool_kernel<<<poolBlocks, TB>>>(batch);
    head_kernel<<<N_GRAPHS, N_CLASSES>>>(Wh, bh, out);
}

// round 3
// speedup vs baseline: 1.2233x; 1.2233x over previous
#include <cuda_runtime.h>

#define N_NODES 100000
#define N_EDGES 1600000
#define HID 128
#define NH4 (HID/4)
#define N_GRAPHS 512
#define N_CLASSES 64
#define BN_EPS 1e-5f
#define SCAN_NB 391   // ceil(N_NODES/256)

// ---------------- scratch (device globals; allocation-free) ----------------
__device__ float g_hW[N_NODES * HID];   // h @ W for current layer
__device__ float g_z [N_NODES * HID];   // pre-BN conv output
__device__ float g_hA[N_NODES * HID];   // layer activations ping
__device__ float g_hB[N_NODES * HID];   // layer activations pong
__device__ float g_dinv[N_NODES];
__device__ int   g_cnt[N_NODES];        // in-degree (without self loop)
__device__ int   g_rowptr[N_NODES + 1];
__device__ int   g_cursor[N_NODES];
__device__ int   g_bsum[SCAN_NB];
__device__ int   g_boff[SCAN_NB];
__device__ int   g_esrc[N_EDGES];       // CSR-sorted source node per edge
__device__ float g_ecoef[N_EDGES];      // dinv[src]*dinv[dst] per sorted edge
__device__ float g_stats[3 * 2 * HID];  // per layer: sum[128], sumsq[128]
__device__ float g_scale[HID];
__device__ float g_shift[HID];
__device__ float g_psum[N_GRAPHS * HID];
__device__ unsigned g_pmax[N_GRAPHS * HID];
__device__ int   g_pcnt[N_GRAPHS];

// ---------------- f32x2 helpers ----------------
__device__ __forceinline__ unsigned long long pk2(float lo, float hi) {
    unsigned long long r;
    asm("mov.b64 %0, {%1, %2};" : "=l"(r) : "f"(lo), "f"(hi));
    return r;
}
__device__ __forceinline__ void upk2(unsigned long long v, float& lo, float& hi) {
    asm("mov.b64 {%0, %1}, %2;" : "=f"(lo), "=f"(hi) : "l"(v));
}
__device__ __forceinline__ void fma2(unsigned long long& d,
                                     unsigned long long a, unsigned long long b) {
    asm("fma.rn.f32x2 %0, %1, %2, %0;" : "+l"(d) : "l"(a), "l"(b));
}

// ---------------- setup kernels ----------------

__global__ __launch_bounds__(256) void zero_kernel() {
    int i = blockIdx.x * blockDim.x + threadIdx.x;
    int stride = gridDim.x * blockDim.x;
    for (int j = i; j < N_NODES; j += stride) { g_cnt[j] = 0; g_cursor[j] = 0; }
    for (int j = i; j < 3 * 2 * HID; j += stride) g_stats[j] = 0.0f;
    for (int j = i; j < N_GRAPHS * HID; j += stride) { g_psum[j] = 0.0f; g_pmax[j] = 0u; }
    for (int j = i; j < N_GRAPHS; j += stride) g_pcnt[j] = 0;
}

__global__ __launch_bounds__(256) void hist_kernel(const int* __restrict__ dst) {
    int e = blockIdx.x * blockDim.x + threadIdx.x;
    if (e < N_EDGES) atomicAdd(&g_cnt[dst[e]], 1);
}

__global__ __launch_bounds__(256) void dinv_kernel() {
    int i = blockIdx.x * blockDim.x + threadIdx.x;
    if (i < N_NODES) g_dinv[i] = rsqrtf((float)g_cnt[i] + 1.0f);
}

// phase A: per-block exclusive scan of g_cnt, block totals -> g_bsum
__global__ __launch_bounds__(256) void scanA_kernel() {
    int t = threadIdx.x, b = blockIdx.x;
    int i = b * 256 + t;
    int v = (i < N_NODES) ? g_cnt[i] : 0;
    int x = v;
#pragma unroll
    for (int o = 1; o < 32; o <<= 1) {
        int y = __shfl_up_sync(0xffffffffu, x, o);
        if ((t & 31) >= o) x += y;
    }
    __shared__ int wsum[8];
    if ((t & 31) == 31) wsum[t >> 5] = x;
    __syncthreads();
    if (t < 32) {
        int s = (t < 8) ? wsum[t] : 0;
#pragma unroll
        for (int o = 1; o < 8; o <<= 1) {
            int y = __shfl_up_sync(0xffffffffu, s, o);
            if (t >= o) s += y;
        }
        if (t < 8) wsum[t] = s;  // inclusive warp sums
    }
    __syncthreads();
    int warpoff = (t >= 32) ? wsum[(t >> 5) - 1] : 0;
    int incl = x + warpoff;
    if (i < N_NODES) g_rowptr[i] = incl - v;  // partial (intra-block) exclusive
    if (t == 255) g_bsum[b] = incl;           // block total
}

// phase B: single-block scan of 391 block sums
__global__ __launch_bounds__(512) void scanB_kernel() {
    __shared__ int sh[512];
    int t = threadIdx.x;
    int v = (t < SCAN_NB) ? g_bsum[t] : 0;
    sh[t] = v;
    __syncthreads();
    for (int o = 1; o < 512; o <<= 1) {
        int y = (t >= o) ? sh[t - o] : 0;
        __syncthreads();
        sh[t] += y;
        __syncthreads();
    }
    if (t < SCAN_NB) g_boff[t] = sh[t] - v;  // exclusive
    if (t == SCAN_NB - 1) g_rowptr[N_NODES] = sh[t];
}

// phase C: add block offsets
__global__ __launch_bounds__(256) void scanC_kernel() {
    int i = blockIdx.x * blockDim.x + threadIdx.x;
    if (i < N_NODES) g_rowptr[i] += g_boff[i >> 8];
}

__global__ __launch_bounds__(256) void scatter_kernel(const int* __restrict__ src,
                                                      const int* __restrict__ dst) {
    int e = blockIdx.x * blockDim.x + threadIdx.x;
    if (e >= N_EDGES) return;
    int d = dst[e], s = src[e];
    int pos = g_rowptr[d] + atomicAdd(&g_cursor[d], 1);
    g_esrc[pos] = s;
    g_ecoef[pos] = g_dinv[s] * g_dinv[d];
}

// ---------------- GEMM: C[M,128] = A[M,128] @ W[128,128] via f32x2 ----------------
// 256 threads, tile 64 rows x 128 cols. tx=col group (4 cols), ty=row group (8 rows
// as 4 row-pairs packed into f32x2 accumulators).
__global__ __launch_bounds__(256) void gemm_kernel(const float* __restrict__ Aext, int sel,
                                                   const float* __restrict__ W) {
    const float* A = (sel == 0) ? Aext : (sel == 1 ? g_hA : g_hB);
    __shared__ __align__(16) float As[16 * 66];   // transposed: As[k][row], stride 66
    __shared__ __align__(16) float Ws[16 * 128];
    const int M = N_NODES;
    int tid = threadIdx.x;
    int tx = tid & 31;              // col group: cols tx*4 .. tx*4+3
    int ty = tid >> 5;              // row group: rows ty*8 .. ty*8+7
    int rowBase = blockIdx.x * 64;

    unsigned long long acc[4][4];   // [row-pair][col], lanes = (row 2i, row 2i+1)
#pragma unroll
    for (int i = 0; i < 4; ++i)
#pragma unroll
        for (int j = 0; j < 4; ++j) acc[i][j] = 0ull;

    for (int kt = 0; kt < 128; kt += 16) {
        // load A tile 64x16 transposed into As[k][r]
        {
            int r = tid >> 2;              // 0..63
            int k = (tid & 3) * 4;         // 0,4,8,12
            int row = rowBase + r;
            float4 v = make_float4(0, 0, 0, 0);
            if (row < M) v = *(const float4*)&A[row * 128 + kt + k];
            As[(k + 0) * 66 + r] = v.x;
            As[(k + 1) * 66 + r] = v.y;
            As[(k + 2) * 66 + r] = v.z;
            As[(k + 3) * 66 + r] = v.w;
        }
        // load W tile 16x128
        {
            int k = tid >> 4;               // 0..15
            int c = (tid & 15) * 8;         // 0..120
            *(float4*)&Ws[k * 128 + c]     = *(const float4*)&W[(kt + k) * 128 + c];
            *(float4*)&Ws[k * 128 + c + 4] = *(const float4*)&W[(kt + k) * 128 + c + 4];
        }
        __syncthreads();
#pragma unroll
        for (int kk = 0; kk < 16; ++kk) {
            float4 wv = *(float4*)&Ws[kk * 128 + tx * 4];
            unsigned long long wb0 = pk2(wv.x, wv.x);
            unsigned long long wb1 = pk2(wv.y, wv.y);
            unsigned long long wb2 = pk2(wv.z, wv.z);
            unsigned long long wb3 = pk2(wv.w, wv.w);
            const float* arow = &As[kk * 66 + ty * 8];
#pragma unroll
            for (int i = 0; i < 4; ++i) {
                unsigned long long a2 = *(const unsigned long long*)&arow[2 * i];
                fma2(acc[i][0], a2, wb0);
                fma2(acc[i][1], a2, wb1);
                fma2(acc[i][2], a2, wb2);
                fma2(acc[i][3], a2, wb3);
            }
        }
        __syncthreads();
    }
#pragma unroll
    for (int i = 0; i < 4; ++i) {
        int r0 = rowBase + ty * 8 + 2 * i;
        float4 lo4, hi4;
        upk2(acc[i][0], lo4.x, hi4.x);
        upk2(acc[i][1], lo4.y, hi4.y);
        upk2(acc[i][2], lo4.z, hi4.z);
        upk2(acc[i][3], lo4.w, hi4.w);
        if (r0 < M)     *(float4*)&g_hW[r0 * 128 + tx * 4]       = lo4;
        if (r0 + 1 < M) *(float4*)&g_hW[(r0 + 1) * 128 + tx * 4] = hi4;
    }
}

// ---------------- aggregate + fused BN stats ----------------
// warp per node: z[i] = sum_e coef*hW[src] + dinv[i]^2 * hW[i] + b
// then block-level reduction of sum / sumsq per channel -> g_stats[layer]
__global__ __launch_bounds__(256) void agg_kernel(const float* __restrict__ b, int layer) {
    __shared__ float ss[8][HID];   // per-warp channel sums
    __shared__ float sq[8][HID];   // per-warp channel sumsq
    int warp = (blockIdx.x * blockDim.x + threadIdx.x) >> 5;
    int w = (threadIdx.x >> 5);
    int lane = threadIdx.x & 31;
    const float4* hw4 = (const float4*)g_hW;
    float4 acc = make_float4(0, 0, 0, 0);
    if (warp < N_NODES) {
        int e0 = g_rowptr[warp], e1 = g_rowptr[warp + 1];
        for (int e = e0; e < e1; ++e) {
            int s = g_esrc[e];
            float c = g_ecoef[e];
            float4 v = hw4[s * NH4 + lane];
            acc.x += c * v.x; acc.y += c * v.y; acc.z += c * v.z; acc.w += c * v.w;
        }
        float di = g_dinv[warp];
        float d2 = di * di;
        float4 v = hw4[warp * NH4 + lane];
        acc.x += d2 * v.x; acc.y += d2 * v.y; acc.z += d2 * v.z; acc.w += d2 * v.w;
        float4 bb = ((const float4*)b)[lane];
        acc.x += bb.x; acc.y += bb.y; acc.z += bb.z; acc.w += bb.w;
        ((float4*)g_z)[warp * NH4 + lane] = acc;
    }
    // stats
    float4 a2 = make_float4(acc.x * acc.x, acc.y * acc.y, acc.z * acc.z, acc.w * acc.w);
    *(float4*)&ss[w][lane * 4] = acc;
    *(float4*)&sq[w][lane * 4] = a2;
    __syncthreads();
    int t = threadIdx.x;
    int arr = t >> 7;        // 0 = sum, 1 = sumsq
    int c = t & 127;
    const float* base = (arr == 0) ? &ss[0][0] : &sq[0][0];
    float total = 0.0f;
#pragma unroll
    for (int ww = 0; ww < 8; ++ww) total += base[ww * HID + c];
    atomicAdd(&g_stats[layer * 2 * HID + arr * HID + c], total);
}

__global__ __launch_bounds__(128) void bnprep_kernel(const float* __restrict__ gam,
                                                     const float* __restrict__ bet, int layer) {
    int c = threadIdx.x;  // 128
    const float* st = &g_stats[layer * 2 * HID];
    const float invN = 1.0f / (float)N_NODES;
    float mu = st[c] * invN;
    float var = st[HID + c] * invN - mu * mu;
    float sc = gam[c] * rsqrtf(var + BN_EPS);
    g_scale[c] = sc;
    g_shift[c] = bet[c] - mu * sc;
}

// y = relu(z*scale + shift (+ residual)); residSel/outSel: 1=g_hA 2=g_hB 0=none
__global__ __launch_bounds__(256) void bn_kernel(int residSel, int outSel) {
    float* out = (outSel == 1) ? g_hA : g_hB;
    const float* res = (residSel == 1) ? g_hA : (residSel == 2 ? g_hB : nullptr);
    int i = blockIdx.x * blockDim.x + threadIdx.x;
    const int total = N_NODES * NH4;
    if (i >= total) return;
    int c4 = (i & (NH4 - 1)) * 4;
    float4 z = ((const float4*)g_z)[i];
    float4 y;
    y.x = z.x * g_scale[c4 + 0] + g_shift[c4 + 0];
    y.y = z.y * g_scale[c4 + 1] + g_shift[c4 + 1];
    y.z = z.z * g_scale[c4 + 2] + g_shift[c4 + 2];
    y.w = z.w * g_scale[c4 + 3] + g_shift[c4 + 3];
    if (res) {
        float4 r = ((const float4*)res)[i];
        y.x += r.x; y.y += r.y; y.z += r.z; y.w += r.w;
    }
    y.x = fmaxf(y.x, 0.0f); y.y = fmaxf(y.y, 0.0f);
    y.z = fmaxf(y.z, 0.0f); y.w = fmaxf(y.w, 0.0f);
    ((float4*)out)[i] = y;
}

__device__ __forceinline__ void pool_flush(int g, int lane, float4 s, float4 m, int cnt) {
    int base = g * HID + lane * 4;
    atomicAdd(&g_psum[base + 0], s.x);
    atomicAdd(&g_psum[base + 1], s.y);
    atomicAdd(&g_psum[base + 2], s.z);
    atomicAdd(&g_psum[base + 3], s.w);
    atomicMax(&g_pmax[base + 0], __float_as_uint(m.x));
    atomicMax(&g_pmax[base + 1], __float_as_uint(m.y));
    atomicMax(&g_pmax[base + 2], __float_as_uint(m.z));
    atomicMax(&g_pmax[base + 3], __float_as_uint(m.w));
    if (lane == 0) atomicAdd(&g_pcnt[g], cnt);
}

// warp handles 16 consecutive nodes (batch is sorted -> few flushes)
__global__ __launch_bounds__(256) void pool_kernel(const int* __restrict__ batch) {
    const int NPW = 16;
    int warp = (blockIdx.x * blockDim.x + threadIdx.x) >> 5;
    int lane = threadIdx.x & 31;
    int n0 = warp * NPW;
    if (n0 >= N_NODES) return;
    int n1 = min(n0 + NPW, N_NODES);
    const float4* h4 = (const float4*)g_hA;  // final activations live in g_hA
    float4 sacc = make_float4(0, 0, 0, 0);
    float4 macc = make_float4(0, 0, 0, 0);
    int cur = batch[n0];
    int cnt = 0;
    for (int n = n0; n < n1; ++n) {
        int g = batch[n];
        if (g != cur) {
            pool_flush(cur, lane, sacc, macc, cnt);
            sacc = make_float4(0, 0, 0, 0);
            macc = make_float4(0, 0, 0, 0);
            cnt = 0; cur = g;
        }
        float4 v = h4[n * NH4 + lane];
        sacc.x += v.x; sacc.y += v.y; sacc.z += v.z; sacc.w += v.w;
        macc.x = fmaxf(macc.x, v.x); macc.y = fmaxf(macc.y, v.y);
        macc.z = fmaxf(macc.z, v.z); macc.w = fmaxf(macc.w, v.w);
        ++cnt;
    }
    pool_flush(cur, lane, sacc, macc, cnt);
}

__global__ __launch_bounds__(64) void head_kernel(const float* __restrict__ Wh,
                                                  const float* __restrict__ bh,
                                                  float* __restrict__ out) {
    int g = blockIdx.x;   // 512
    int c = threadIdx.x;  // 64
    float cntf = (float)g_pcnt[g];
    float inv = 1.0f / fmaxf(cntf, 1.0f);
    float acc = bh[c];
    for (int k = 0; k < HID; ++k) {
        float s = g_psum[g * HID + k];
        float m = s * inv;
        float mx = __uint_as_float(g_pmax[g * HID + k]);
        acc += m * Wh[k * N_CLASSES + c]
             + s * Wh[(HID + k) * N_CLASSES + c]
             + mx * Wh[(2 * HID + k) * N_CLASSES + c];
    }
    out[g * N_CLASSES + c] = acc;
}

// ---------------- launch ----------------
extern "C" void kernel_launch(void* const* d_in, const int* in_sizes, int n_in,
                              void* d_out, int out_size) {
    const float* x    = (const float*)d_in[0];
    const int*   ei   = (const int*)d_in[1];
    const int*   src  = ei;
    const int*   dst  = ei + N_EDGES;
    const int*   batch = (const int*)d_in[2];
    const float* W1 = (const float*)d_in[3];
    const float* b1 = (const float*)d_in[4];
    const float* g1 = (const float*)d_in[5];
    const float* be1 = (const float*)d_in[6];
    const float* W2 = (const float*)d_in[7];
    const float* b2 = (const float*)d_in[8];
    const float* g2 = (const float*)d_in[9];
    const float* be2 = (const float*)d_in[10];
    const float* W3 = (const float*)d_in[11];
    const float* b3 = (const float*)d_in[12];
    const float* g3 = (const float*)d_in[13];
    const float* be3 = (const float*)d_in[14];
    const float* Wh = (const float*)d_in[15];
    const float* bh = (const float*)d_in[16];
    float* out = (float*)d_out;

    const int TB = 256;
    const int edgeBlocks = (N_EDGES + TB - 1) / TB;
    const int nodeBlocks = (N_NODES + TB - 1) / TB;
    const int gemmBlocks = (N_NODES + 63) / 64;
    const int aggBlocks = (N_NODES + 7) / 8;              // warp per node, 8/block
    const int bnBlocks = (N_NODES * NH4 + TB - 1) / TB;
    const int poolWarps = (N_NODES + 15) / 16;
    const int poolBlocks = (poolWarps * 32 + TB - 1) / TB;

    zero_kernel<<<256, TB>>>();
    hist_kernel<<<edgeBlocks, TB>>>(dst);
    dinv_kernel<<<nodeBlocks, TB>>>();
    scanA_kernel<<<SCAN_NB, 256>>>();
    scanB_kernel<<<1, 512>>>();
    scanC_kernel<<<nodeBlocks, TB>>>();
    scatter_kernel<<<edgeBlocks, TB>>>(src, dst);

    // ---- layer 1: x -> g_hA ----
    gemm_kernel<<<gemmBlocks, TB>>>(x, 0, W1);
    agg_kernel<<<aggBlocks, TB>>>(b1, 0);
    bnprep_kernel<<<1, 128>>>(g1, be1, 0);
    bn_kernel<<<bnBlocks, TB>>>(0, 1);

    // ---- layer 2: g_hA -> g_hB (residual g_hA) ----
    gemm_kernel<<<gemmBlocks, TB>>>(nullptr, 1, W2);
    agg_kernel<<<aggBlocks, TB>>>(b2, 1);
    bnprep_kernel<<<1, 128>>>(g2, be2, 1);
    bn_kernel<<<bnBlocks, TB>>>(1, 2);

    // ---- layer 3: g_hB -> g_hA (residual g_hB) ----
    gemm_kernel<<<gemmBlocks, TB>>>(nullptr, 2, W3);
    agg_kernel<<<aggBlocks, TB>>>(b3, 2);
    bnprep_kernel<<<1, 128>>>(g3, be3, 2);
    bn_kernel<<<bnBlocks, TB>>>(2, 1);

    // ---- pooling + head ----
    pool_kernel<<<poolBlocks, TB>>>(batch);
    head_kernel<<<N_GRAPHS, N_CLASSES>>>(Wh, bh, out);
}

// round 5
// speedup vs baseline: 1.3343x; 1.0907x over previous
#include <cuda_runtime.h>
#include <cuda_fp16.h>

#define N_NODES 100000
#define N_EDGES 1600000
#define HID 128
#define NH4 (HID/4)
#define N_GRAPHS 512
#define N_CLASSES 64
#define BN_EPS 1e-5f
#define SCAN_NB 391   // ceil(N_NODES/256)

// ---------------- scratch (device globals; allocation-free) ----------------
__device__ uint2 g_hWh[N_NODES * 32];   // h @ W, packed fp16 (2x half2 per uint2)
__device__ float g_z [N_NODES * HID];   // pre-BN conv output
__device__ float g_hA[N_NODES * HID];   // h1
__device__ float g_hB[N_NODES * HID];   // h2
__device__ float g_dinv[N_NODES];
__device__ int   g_cnt[N_NODES];
__device__ int   g_rowptr[N_NODES + 1];
__device__ int   g_cursor[N_NODES];
__device__ int   g_bsum[SCAN_NB];
__device__ int   g_boff[SCAN_NB];
__device__ int   g_esrc[N_EDGES];
__device__ float g_ecoef[N_EDGES];
__device__ float g_stats[3 * 2 * HID];
__device__ float g_scale[HID];
__device__ float g_shift[HID];
__device__ float g_psum[N_GRAPHS * HID];
__device__ unsigned g_pmax[N_GRAPHS * HID];
__device__ int   g_pcnt[N_GRAPHS];

// ---------------- f32x2 helpers ----------------
__device__ __forceinline__ unsigned long long pk2(float lo, float hi) {
    unsigned long long r;
    asm("mov.b64 %0, {%1, %2};" : "=l"(r) : "f"(lo), "f"(hi));
    return r;
}
__device__ __forceinline__ void upk2(unsigned long long v, float& lo, float& hi) {
    asm("mov.b64 {%0, %1}, %2;" : "=f"(lo), "=f"(hi) : "l"(v));
}
__device__ __forceinline__ void fma2(unsigned long long& d,
                                     unsigned long long a, unsigned long long b) {
    asm("fma.rn.f32x2 %0, %1, %2, %0;" : "+l"(d) : "l"(a), "l"(b));
}

// ---------------- setup kernels ----------------

__global__ __launch_bounds__(256) void zero_kernel() {
    int i = blockIdx.x * blockDim.x + threadIdx.x;
    int stride = gridDim.x * blockDim.x;
    for (int j = i; j < N_NODES; j += stride) { g_cnt[j] = 0; g_cursor[j] = 0; }
    for (int j = i; j < 3 * 2 * HID; j += stride) g_stats[j] = 0.0f;
    for (int j = i; j < N_GRAPHS * HID; j += stride) { g_psum[j] = 0.0f; g_pmax[j] = 0u; }
    for (int j = i; j < N_GRAPHS; j += stride) g_pcnt[j] = 0;
}

__global__ __launch_bounds__(256) void hist_kernel(const int* __restrict__ dst) {
    int e = blockIdx.x * blockDim.x + threadIdx.x;
    if (e < N_EDGES) atomicAdd(&g_cnt[dst[e]], 1);
}

__global__ __launch_bounds__(256) void dinv_kernel() {
    int i = blockIdx.x * blockDim.x + threadIdx.x;
    if (i < N_NODES) g_dinv[i] = rsqrtf((float)g_cnt[i] + 1.0f);
}

__global__ __launch_bounds__(256) void scanA_kernel() {
    int t = threadIdx.x, b = blockIdx.x;
    int i = b * 256 + t;
    int v = (i < N_NODES) ? g_cnt[i] : 0;
    int x = v;
#pragma unroll
    for (int o = 1; o < 32; o <<= 1) {
        int y = __shfl_up_sync(0xffffffffu, x, o);
        if ((t & 31) >= o) x += y;
    }
    __shared__ int wsum[8];
    if ((t & 31) == 31) wsum[t >> 5] = x;
    __syncthreads();
    if (t < 32) {
        int s = (t < 8) ? wsum[t] : 0;
#pragma unroll
        for (int o = 1; o < 8; o <<= 1) {
            int y = __shfl_up_sync(0xffffffffu, s, o);
            if (t >= o) s += y;
        }
        if (t < 8) wsum[t] = s;
    }
    __syncthreads();
    int warpoff = (t >= 32) ? wsum[(t >> 5) - 1] : 0;
    int incl = x + warpoff;
    if (i < N_NODES) g_rowptr[i] = incl - v;
    if (t == 255) g_bsum[b] = incl;
}

__global__ __launch_bounds__(512) void scanB_kernel() {
    __shared__ int sh[512];
    int t = threadIdx.x;
    int v = (t < SCAN_NB) ? g_bsum[t] : 0;
    sh[t] = v;
    __syncthreads();
    for (int o = 1; o < 512; o <<= 1) {
        int y = (t >= o) ? sh[t - o] : 0;
        __syncthreads();
        sh[t] += y;
        __syncthreads();
    }
    if (t < SCAN_NB) g_boff[t] = sh[t] - v;
    if (t == SCAN_NB - 1) g_rowptr[N_NODES] = sh[t];
}

__global__ __launch_bounds__(256) void scanC_kernel() {
    int i = blockIdx.x * blockDim.x + threadIdx.x;
    if (i < N_NODES) g_rowptr[i] += g_boff[i >> 8];
}

__global__ __launch_bounds__(256) void scatter_kernel(const int* __restrict__ src,
                                                      const int* __restrict__ dst) {
    int e = blockIdx.x * blockDim.x + threadIdx.x;
    if (e >= N_EDGES) return;
    int d = dst[e], s = src[e];
    int pos = g_rowptr[d] + atomicAdd(&g_cursor[d], 1);
    g_esrc[pos] = s;
    g_ecoef[pos] = g_dinv[s] * g_dinv[d];
}

// ---------------- fused GEMM ----------------
// mode 0: A = Aext (x), no BN, no h store.
// mode 1: A = relu(bn(g_z)), store h -> g_hA.
// mode 2: A = relu(bn(g_z) + g_hA), store h -> g_hB.
// Then C = A @ W written to g_hWh in fp16. 256 threads, 64x128 tile, f32x2 FMAs.
__global__ __launch_bounds__(256) void gemm_kernel(const float* __restrict__ Aext,
                                                   const float* __restrict__ W,
                                                   int mode) {
    const float* Ain = (mode == 0) ? Aext : g_z;
    const float* res = (mode == 2) ? g_hA : nullptr;
    float* hout = (mode == 1) ? g_hA : ((mode == 2) ? g_hB : nullptr);
    __shared__ __align__(16) float As[16 * 66];   // transposed: As[k][row]
    __shared__ __align__(16) float Ws[16 * 128];
    const int M = N_NODES;
    int tid = threadIdx.x;
    int tx = tid & 31;
    int ty = tid >> 5;
    int rowBase = blockIdx.x * 64;

    unsigned long long acc[4][4];
#pragma unroll
    for (int i = 0; i < 4; ++i)
#pragma unroll
        for (int j = 0; j < 4; ++j) acc[i][j] = 0ull;

    for (int kt = 0; kt < 128; kt += 16) {
        {
            int r = tid >> 2;
            int k = (tid & 3) * 4;
            int row = rowBase + r;
            float4 v = make_float4(0, 0, 0, 0);
            if (row < M) {
                v = *(const float4*)&Ain[row * 128 + kt + k];
                if (mode != 0) {
                    float4 sc = *(const float4*)&g_scale[kt + k];
                    float4 sh = *(const float4*)&g_shift[kt + k];
                    v.x = v.x * sc.x + sh.x;
                    v.y = v.y * sc.y + sh.y;
                    v.z = v.z * sc.z + sh.z;
                    v.w = v.w * sc.w + sh.w;
                    if (mode == 2) {
                        float4 rr = *(const float4*)&res[row * 128 + kt + k];
                        v.x += rr.x; v.y += rr.y; v.z += rr.z; v.w += rr.w;
                    }
                    v.x = fmaxf(v.x, 0.0f); v.y = fmaxf(v.y, 0.0f);
                    v.z = fmaxf(v.z, 0.0f); v.w = fmaxf(v.w, 0.0f);
                    *(float4*)&hout[row * 128 + kt + k] = v;
                }
            }
            As[(k + 0) * 66 + r] = v.x;
            As[(k + 1) * 66 + r] = v.y;
            As[(k + 2) * 66 + r] = v.z;
            As[(k + 3) * 66 + r] = v.w;
        }
        {
            int k = tid >> 4;
            int c = (tid & 15) * 8;
            *(float4*)&Ws[k * 128 + c]     = *(const float4*)&W[(kt + k) * 128 + c];
            *(float4*)&Ws[k * 128 + c + 4] = *(const float4*)&W[(kt + k) * 128 + c + 4];
        }
        __syncthreads();
#pragma unroll
        for (int kk = 0; kk < 16; ++kk) {
            float4 wv = *(float4*)&Ws[kk * 128 + tx * 4];
            unsigned long long wb0 = pk2(wv.x, wv.x);
            unsigned long long wb1 = pk2(wv.y, wv.y);
            unsigned long long wb2 = pk2(wv.z, wv.z);
            unsigned long long wb3 = pk2(wv.w, wv.w);
            const float* arow = &As[kk * 66 + ty * 8];
#pragma unroll
            for (int i = 0; i < 4; ++i) {
                unsigned long long a2 = *(const unsigned long long*)&arow[2 * i];
                fma2(acc[i][0], a2, wb0);
                fma2(acc[i][1], a2, wb1);
                fma2(acc[i][2], a2, wb2);
                fma2(acc[i][3], a2, wb3);
            }
        }
        __syncthreads();
    }
#pragma unroll
    for (int i = 0; i < 4; ++i) {
        int r0 = rowBase + ty * 8 + 2 * i;
        float4 lo4, hi4;
        upk2(acc[i][0], lo4.x, hi4.x);
        upk2(acc[i][1], lo4.y, hi4.y);
        upk2(acc[i][2], lo4.z, hi4.z);
        upk2(acc[i][3], lo4.w, hi4.w);
        if (r0 < M) {
            __half2 p0 = __floats2half2_rn(lo4.x, lo4.y);
            __half2 p1 = __floats2half2_rn(lo4.z, lo4.w);
            uint2 u;
            u.x = *(unsigned*)&p0; u.y = *(unsigned*)&p1;
            g_hWh[r0 * 32 + tx] = u;
        }
        if (r0 + 1 < M) {
            __half2 p0 = __floats2half2_rn(hi4.x, hi4.y);
            __half2 p1 = __floats2half2_rn(hi4.z, hi4.w);
            uint2 u;
            u.x = *(unsigned*)&p0; u.y = *(unsigned*)&p1;
            g_hWh[(r0 + 1) * 32 + tx] = u;
        }
    }
}

// ---------------- aggregate (fp16 gather) + fused BN stats ----------------
__global__ __launch_bounds__(256) void agg_kernel(const float* __restrict__ b, int layer) {
    __shared__ float ss[8][HID];
    __shared__ float sq[8][HID];
    int warp = (blockIdx.x * blockDim.x + threadIdx.x) >> 5;
    int w = (threadIdx.x >> 5);
    int lane = threadIdx.x & 31;
    float4 acc = make_float4(0, 0, 0, 0);
    if (warp < N_NODES) {
        int e0 = g_rowptr[warp], e1 = g_rowptr[warp + 1];
        int s = 0; float c = 0.0f;
        if (e0 < e1) { s = g_esrc[e0]; c = g_ecoef[e0]; }
        for (int e = e0; e < e1; ++e) {
            int sn = 0; float cn = 0.0f;
            if (e + 1 < e1) { sn = g_esrc[e + 1]; cn = g_ecoef[e + 1]; }
            uint2 u = g_hWh[s * 32 + lane];
            __half2 h0 = *(__half2*)&u.x;
            __half2 h1 = *(__half2*)&u.y;
            float2 f0 = __half22float2(h0);
            float2 f1 = __half22float2(h1);
            acc.x += c * f0.x; acc.y += c * f0.y;
            acc.z += c * f1.x; acc.w += c * f1.y;
            s = sn; c = cn;
        }
        float di = g_dinv[warp];
        float d2 = di * di;
        uint2 u = g_hWh[warp * 32 + lane];
        __half2 h0 = *(__half2*)&u.x;
        __half2 h1 = *(__half2*)&u.y;
        float2 f0 = __half22float2(h0);
        float2 f1 = __half22float2(h1);
        acc.x += d2 * f0.x; acc.y += d2 * f0.y;
        acc.z += d2 * f1.x; acc.w += d2 * f1.y;
        float4 bb = ((const float4*)b)[lane];
        acc.x += bb.x; acc.y += bb.y; acc.z += bb.z; acc.w += bb.w;
        ((float4*)g_z)[warp * NH4 + lane] = acc;
    }
    float4 a2 = make_float4(acc.x * acc.x, acc.y * acc.y, acc.z * acc.z, acc.w * acc.w);
    *(float4*)&ss[w][lane * 4] = acc;
    *(float4*)&sq[w][lane * 4] = a2;
    __syncthreads();
    int t = threadIdx.x;
    int arr = t >> 7;
    int c = t & 127;
    const float* base = (arr == 0) ? &ss[0][0] : &sq[0][0];
    float total = 0.0f;
#pragma unroll
    for (int ww = 0; ww < 8; ++ww) total += base[ww * HID + c];
    atomicAdd(&g_stats[layer * 2 * HID + arr * HID + c], total);
}

__global__ __launch_bounds__(128) void bnprep_kernel(const float* __restrict__ gam,
                                                     const float* __restrict__ bet, int layer) {
    int c = threadIdx.x;
    const float* st = &g_stats[layer * 2 * HID];
    const float invN = 1.0f / (float)N_NODES;
    float mu = st[c] * invN;
    float var = st[HID + c] * invN - mu * mu;
    float sc = gam[c] * rsqrtf(var + BN_EPS);
    g_scale[c] = sc;
    g_shift[c] = bet[c] - mu * sc;
}

__device__ __forceinline__ void pool_flush(int g, int lane, float4 s, float4 m, int cnt) {
    int base = g * HID + lane * 4;
    atomicAdd(&g_psum[base + 0], s.x);
    atomicAdd(&g_psum[base + 1], s.y);
    atomicAdd(&g_psum[base + 2], s.z);
    atomicAdd(&g_psum[base + 3], s.w);
    atomicMax(&g_pmax[base + 0], __float_as_uint(m.x));
    atomicMax(&g_pmax[base + 1], __float_as_uint(m.y));
    atomicMax(&g_pmax[base + 2], __float_as_uint(m.z));
    atomicMax(&g_pmax[base + 3], __float_as_uint(m.w));
    if (lane == 0) atomicAdd(&g_pcnt[g], cnt);
}

// pool with fused layer-3 BN + residual + relu: h3 = relu(z*sc+sh + h2)
__global__ __launch_bounds__(256) void pool_kernel(const int* __restrict__ batch) {
    const int NPW = 16;
    int warp = (blockIdx.x * blockDim.x + threadIdx.x) >> 5;
    int lane = threadIdx.x & 31;
    int n0 = warp * NPW;
    if (n0 >= N_NODES) return;
    int n1 = min(n0 + NPW, N_NODES);
    const float4* z4 = (const float4*)g_z;
    const float4* r4 = (const float4*)g_hB;
    float4 sc = *(const float4*)&g_scale[lane * 4];
    float4 sh = *(const float4*)&g_shift[lane * 4];
    float4 sacc = make_float4(0, 0, 0, 0);
    float4 macc = make_float4(0, 0, 0, 0);
    int cur = batch[n0];
    int cnt = 0;
    for (int n = n0; n < n1; ++n) {
        int g = batch[n];
        if (g != cur) {
            pool_flush(cur, lane, sacc, macc, cnt);
            sacc = make_float4(0, 0, 0, 0);
            macc = make_float4(0, 0, 0, 0);
            cnt = 0; cur = g;
        }
        float4 z = z4[n * NH4 + lane];
        float4 r = r4[n * NH4 + lane];
        float4 v;
        v.x = fmaxf(z.x * sc.x + sh.x + r.x, 0.0f);
        v.y = fmaxf(z.y * sc.y + sh.y + r.y, 0.0f);
        v.z = fmaxf(z.z * sc.z + sh.z + r.z, 0.0f);
        v.w = fmaxf(z.w * sc.w + sh.w + r.w, 0.0f);
        sacc.x += v.x; sacc.y += v.y; sacc.z += v.z; sacc.w += v.w;
        macc.x = fmaxf(macc.x, v.x); macc.y = fmaxf(macc.y, v.y);
        macc.z = fmaxf(macc.z, v.z); macc.w = fmaxf(macc.w, v.w);
        ++cnt;
    }
    pool_flush(cur, lane, sacc, macc, cnt);
}

__global__ __launch_bounds__(64) void head_kernel(const float* __restrict__ Wh,
                                                  const float* __restrict__ bh,
                                                  float* __restrict__ out) {
    int g = blockIdx.x;
    int c = threadIdx.x;
    float cntf = (float)g_pcnt[g];
    float inv = 1.0f / fmaxf(cntf, 1.0f);
    float acc = bh[c];
    for (int k = 0; k < HID; ++k) {
        float s = g_psum[g * HID + k];
        float m = s * inv;
        float mx = __uint_as_float(g_pmax[g * HID + k]);
        acc += m * Wh[k * N_CLASSES + c]
             + s * Wh[(HID + k) * N_CLASSES + c]
             + mx * Wh[(2 * HID + k) * N_CLASSES + c];
    }
    out[g * N_CLASSES + c] = acc;
}

// ---------------- launch ----------------
extern "C" void kernel_launch(void* const* d_in, const int* in_sizes, int n_in,
                              void* d_out, int out_size) {
    const float* x    = (const float*)d_in[0];
    const int*   ei   = (const int*)d_in[1];
    const int*   src  = ei;
    const int*   dst  = ei + N_EDGES;
    const int*   batch = (const int*)d_in[2];
    const float* W1 = (const float*)d_in[3];
    const float* b1 = (const float*)d_in[4];
    const float* g1 = (const float*)d_in[5];
    const float* be1 = (const float*)d_in[6];
    const float* W2 = (const float*)d_in[7];
    const float* b2 = (const float*)d_in[8];
    const float* g2 = (const float*)d_in[9];
    const float* be2 = (const float*)d_in[10];
    const float* W3 = (const float*)d_in[11];
    const float* b3 = (const float*)d_in[12];
    const float* g3 = (const float*)d_in[13];
    const float* be3 = (const float*)d_in[14];
    const float* Wh = (const float*)d_in[15];
    const float* bh = (const float*)d_in[16];
    float* out = (float*)d_out;

    const int TB = 256;
    const int edgeBlocks = (N_EDGES + TB - 1) / TB;
    const int nodeBlocks = (N_NODES + TB - 1) / TB;
    const int gemmBlocks = (N_NODES + 63) / 64;
    const int aggBlocks = (N_NODES + 7) / 8;
    const int poolWarps = (N_NODES + 15) / 16;
    const int poolBlocks = (poolWarps * 32 + TB - 1) / TB;

    zero_kernel<<<256, TB>>>();
    hist_kernel<<<edgeBlocks, TB>>>(dst);
    dinv_kernel<<<nodeBlocks, TB>>>();
    scanA_kernel<<<SCAN_NB, 256>>>();
    scanB_kernel<<<1, 512>>>();
    scanC_kernel<<<nodeBlocks, TB>>>();
    scatter_kernel<<<edgeBlocks, TB>>>(src, dst);

    // layer 1: A = x (raw)
    gemm_kernel<<<gemmBlocks, TB>>>(x, W1, 0);
    agg_kernel<<<aggBlocks, TB>>>(b1, 0);
    bnprep_kernel<<<1, 128>>>(g1, be1, 0);

    // layer 2: A = h1 = relu(bn1(z1)), h1 -> g_hA
    gemm_kernel<<<gemmBlocks, TB>>>(nullptr, W2, 1);
    agg_kernel<<<aggBlocks, TB>>>(b2, 1);
    bnprep_kernel<<<1, 128>>>(g2, be2, 1);

    // layer 3: A = h2 = relu(bn2(z2) + h1), h2 -> g_hB
    gemm_kernel<<<gemmBlocks, TB>>>(nullptr, W3, 2);
    agg_kernel<<<aggBlocks, TB>>>(b3, 2);
    bnprep_kernel<<<1, 128>>>(g3, be3, 2);

    // pool (fused bn3 + residual h2) + head
    pool_kernel<<<poolBlocks, TB>>>(batch);
    head_kernel<<<N_GRAPHS, N_CLASSES>>>(Wh, bh, out);
}

// round 7
// speedup vs baseline: 1.4433x; 1.0817x over previous
#include <cuda_runtime.h>
#include <cuda_fp16.h>
#include <cstdint>

#define N_NODES 100000
#define N_EDGES 1600000
#define HID 128
#define NH4 (HID/4)
#define N_GRAPHS 512
#define N_CLASSES 64
#define BN_EPS 1e-5f
#define SCAN_NB 391   // ceil(N_NODES/256)

#define TILE_M 128
#define MMA_BLOCKS ((N_NODES + TILE_M - 1) / TILE_M)   // 782
#define APAD 136                                        // halves per smem row (272B, conflict-free LDSM)
#define SMEM_MMA_BYTES (2 * 128 * APAD * 2)             // A + B fp16 tiles = 69632

// ---------------- scratch (device globals; allocation-free) ----------------
__device__ __align__(16) unsigned g_hW2[N_NODES * 64]; // h @ W payload, half2 per u32 (col pair)
__device__ float g_z [N_NODES * HID];   // pre-BN conv output
__device__ float g_hA[N_NODES * HID];   // h1
__device__ float g_hB[N_NODES * HID];   // h2
__device__ float g_dinv[N_NODES];
__device__ int   g_cnt[N_NODES];
__device__ int   g_rowptr[N_NODES + 1];
__device__ int   g_cursor[N_NODES];
__device__ int   g_bsum[SCAN_NB];
__device__ int   g_boff[SCAN_NB];
__device__ int   g_esrc[N_EDGES];
__device__ float g_ecoef[N_EDGES];
__device__ float g_stats[3 * 2 * HID];
__device__ float g_scale[HID];
__device__ float g_shift[HID];
__device__ float g_psum[N_GRAPHS * HID];
__device__ unsigned g_pmax[N_GRAPHS * HID];
__device__ int   g_pcnt[N_GRAPHS];

// ---------------- warp-MMA helpers (baseline PTX, no tcgen05) ----------------
__device__ __forceinline__ uint32_t smem_u32(const void* p) {
    uint32_t a;
    asm("{ .reg .u64 t; cvta.to.shared.u64 t, %1; cvt.u32.u64 %0, t; }" : "=r"(a) : "l"(p));
    return a;
}
__device__ __forceinline__ void ldsm_x4(uint32_t* r, uint32_t addr) {
    asm volatile("ldmatrix.sync.aligned.m8n8.x4.shared.b16 {%0,%1,%2,%3}, [%4];"
                 : "=r"(r[0]), "=r"(r[1]), "=r"(r[2]), "=r"(r[3]) : "r"(addr));
}
__device__ __forceinline__ void ldsm_x4_t(uint32_t* r, uint32_t addr) {
    asm volatile("ldmatrix.sync.aligned.m8n8.x4.trans.shared.b16 {%0,%1,%2,%3}, [%4];"
                 : "=r"(r[0]), "=r"(r[1]), "=r"(r[2]), "=r"(r[3]) : "r"(addr));
}
__device__ __forceinline__ void mma16816(float* c, const uint32_t* a, const uint32_t* b) {
    asm volatile(
        "mma.sync.aligned.m16n8k16.row.col.f32.f16.f16.f32 "
        "{%0,%1,%2,%3}, {%4,%5,%6,%7}, {%8,%9}, {%0,%1,%2,%3};"
        : "+f"(c[0]), "+f"(c[1]), "+f"(c[2]), "+f"(c[3])
        : "r"(a[0]), "r"(a[1]), "r"(a[2]), "r"(a[3]), "r"(b[0]), "r"(b[1]));
}

// ---------------- setup kernels ----------------

__global__ __launch_bounds__(256) void zero_kernel() {
    int i = blockIdx.x * blockDim.x + threadIdx.x;
    int stride = gridDim.x * blockDim.x;
    for (int j = i; j < N_NODES; j += stride) { g_cnt[j] = 0; g_cursor[j] = 0; }
    for (int j = i; j < 3 * 2 * HID; j += stride) g_stats[j] = 0.0f;
    for (int j = i; j < N_GRAPHS * HID; j += stride) { g_psum[j] = 0.0f; g_pmax[j] = 0u; }
    for (int j = i; j < N_GRAPHS; j += stride) g_pcnt[j] = 0;
}

__global__ __launch_bounds__(256) void hist_kernel(const int* __restrict__ dst) {
    int e = blockIdx.x * blockDim.x + threadIdx.x;
    if (e < N_EDGES) atomicAdd(&g_cnt[dst[e]], 1);
}

__global__ __launch_bounds__(256) void dinv_kernel() {
    int i = blockIdx.x * blockDim.x + threadIdx.x;
    if (i < N_NODES) g_dinv[i] = rsqrtf((float)g_cnt[i] + 1.0f);
}

__global__ __launch_bounds__(256) void scanA_kernel() {
    int t = threadIdx.x, b = blockIdx.x;
    int i = b * 256 + t;
    int v = (i < N_NODES) ? g_cnt[i] : 0;
    int x = v;
#pragma unroll
    for (int o = 1; o < 32; o <<= 1) {
        int y = __shfl_up_sync(0xffffffffu, x, o);
        if ((t & 31) >= o) x += y;
    }
    __shared__ int wsum[8];
    if ((t & 31) == 31) wsum[t >> 5] = x;
    __syncthreads();
    if (t < 32) {
        int s = (t < 8) ? wsum[t] : 0;
#pragma unroll
        for (int o = 1; o < 8; o <<= 1) {
            int y = __shfl_up_sync(0xffffffffu, s, o);
            if (t >= o) s += y;
        }
        if (t < 8) wsum[t] = s;
    }
    __syncthreads();
    int warpoff = (t >= 32) ? wsum[(t >> 5) - 1] : 0;
    int incl = x + warpoff;
    if (i < N_NODES) g_rowptr[i] = incl - v;
    if (t == 255) g_bsum[b] = incl;
}

__global__ __launch_bounds__(512) void scanB_kernel() {
    __shared__ int sh[512];
    int t = threadIdx.x;
    int v = (t < SCAN_NB) ? g_bsum[t] : 0;
    sh[t] = v;
    __syncthreads();
    for (int o = 1; o < 512; o <<= 1) {
        int y = (t >= o) ? sh[t - o] : 0;
        __syncthreads();
        sh[t] += y;
        __syncthreads();
    }
    if (t < SCAN_NB) g_boff[t] = sh[t] - v;
    if (t == SCAN_NB - 1) g_rowptr[N_NODES] = sh[t];
}

__global__ __launch_bounds__(256) void scanC_kernel() {
    int i = blockIdx.x * blockDim.x + threadIdx.x;
    if (i < N_NODES) g_rowptr[i] += g_boff[i >> 8];
}

__global__ __launch_bounds__(256) void scatter_kernel(const int* __restrict__ src,
                                                      const int* __restrict__ dst) {
    int e = blockIdx.x * blockDim.x + threadIdx.x;
    if (e >= N_EDGES) return;
    int d = dst[e], s = src[e];
    int pos = g_rowptr[d] + atomicAdd(&g_cursor[d], 1);
    g_esrc[pos] = s;
    g_ecoef[pos] = g_dinv[s] * g_dinv[d];
}

// ---------------- HMMA GEMM: C = A @ W -> g_hW2 (fp16 payload) ----------------
// mode 0: A = Aext (x). mode 1: A = relu(bn(g_z)), h -> g_hA.
// mode 2: A = relu(bn(g_z) + g_hA), h -> g_hB.
__global__ __launch_bounds__(256) void mma_kernel(const float* __restrict__ Aext,
                                                  const float* __restrict__ W,
                                                  int mode) {
    extern __shared__ __align__(16) __half smh[];
    __half* As = smh;                  // [128][APAD]  rows = m, cols = k
    __half* Bs = smh + 128 * APAD;     // [128][APAD]  rows = k, cols = n
    const float* Ain = (mode == 0) ? Aext : g_z;
    const float* res = (mode == 2) ? g_hA : nullptr;
    float* hout = (mode == 1) ? g_hA : ((mode == 2) ? g_hB : nullptr);

    int tid = threadIdx.x;
    int lane = tid & 31, wid = tid >> 5;
    int rowBase = blockIdx.x * TILE_M;

    // ---- stage A (BN fusion) and B = W, both fp16 ----
    {
        int r = tid >> 1;            // 0..127
        int hf = (tid & 1) * 64;     // half-row offset
        int row = rowBase + r;
        bool valid = row < N_NODES;
#pragma unroll
        for (int cc = 0; cc < 8; ++cc) {
            int c = hf + cc * 8;
            float4 v0 = make_float4(0, 0, 0, 0), v1 = make_float4(0, 0, 0, 0);
            if (valid) {
                v0 = *(const float4*)&Ain[row * 128 + c];
                v1 = *(const float4*)&Ain[row * 128 + c + 4];
                if (mode != 0) {
                    float4 s0 = *(const float4*)&g_scale[c];
                    float4 s1 = *(const float4*)&g_scale[c + 4];
                    float4 h0 = *(const float4*)&g_shift[c];
                    float4 h1 = *(const float4*)&g_shift[c + 4];
                    v0.x = v0.x * s0.x + h0.x; v0.y = v0.y * s0.y + h0.y;
                    v0.z = v0.z * s0.z + h0.z; v0.w = v0.w * s0.w + h0.w;
                    v1.x = v1.x * s1.x + h1.x; v1.y = v1.y * s1.y + h1.y;
                    v1.z = v1.z * s1.z + h1.z; v1.w = v1.w * s1.w + h1.w;
                    if (mode == 2) {
                        float4 r0 = *(const float4*)&res[row * 128 + c];
                        float4 r1 = *(const float4*)&res[row * 128 + c + 4];
                        v0.x += r0.x; v0.y += r0.y; v0.z += r0.z; v0.w += r0.w;
                        v1.x += r1.x; v1.y += r1.y; v1.z += r1.z; v1.w += r1.w;
                    }
                    v0.x = fmaxf(v0.x, 0.0f); v0.y = fmaxf(v0.y, 0.0f);
                    v0.z = fmaxf(v0.z, 0.0f); v0.w = fmaxf(v0.w, 0.0f);
                    v1.x = fmaxf(v1.x, 0.0f); v1.y = fmaxf(v1.y, 0.0f);
                    v1.z = fmaxf(v1.z, 0.0f); v1.w = fmaxf(v1.w, 0.0f);
                    *(float4*)&hout[row * 128 + c] = v0;
                    *(float4*)&hout[row * 128 + c + 4] = v1;
                }
            }
            __half2 p0 = __floats2half2_rn(v0.x, v0.y);
            __half2 p1 = __floats2half2_rn(v0.z, v0.w);
            __half2 p2 = __floats2half2_rn(v1.x, v1.y);
            __half2 p3 = __floats2half2_rn(v1.z, v1.w);
            uint4 u;
            u.x = *(unsigned*)&p0; u.y = *(unsigned*)&p1;
            u.z = *(unsigned*)&p2; u.w = *(unsigned*)&p3;
            *(uint4*)&As[r * APAD + c] = u;

            // B: k row = r, same column span
            float4 w0 = *(const float4*)&W[r * 128 + c];
            float4 w1 = *(const float4*)&W[r * 128 + c + 4];
            __half2 q0 = __floats2half2_rn(w0.x, w0.y);
            __half2 q1 = __floats2half2_rn(w0.z, w0.w);
            __half2 q2 = __floats2half2_rn(w1.x, w1.y);
            __half2 q3 = __floats2half2_rn(w1.z, w1.w);
            uint4 uw;
            uw.x = *(unsigned*)&q0; uw.y = *(unsigned*)&q1;
            uw.z = *(unsigned*)&q2; uw.w = *(unsigned*)&q3;
            *(uint4*)&Bs[r * APAD + c] = uw;
        }
    }
    __syncthreads();

    // ---- warp tiles: 4x2 warps, each 32(m) x 64(n) ----
    int wm = wid & 3;       // 0..3 -> m offset wm*32
    int wn = wid >> 2;      // 0..1 -> n offset wn*64
    float acc[2][8][4];
#pragma unroll
    for (int mt = 0; mt < 2; ++mt)
#pragma unroll
        for (int nt = 0; nt < 8; ++nt)
#pragma unroll
            for (int j = 0; j < 4; ++j) acc[mt][nt][j] = 0.0f;

    uint32_t As_base = smem_u32(As);
    uint32_t Bs_base = smem_u32(Bs);
    // ldmatrix lane addressing
    int a_row = wm * 32 + (lane & 7) + ((lane >> 3) & 1) * 8;  // + mt*16
    int a_col = (lane >> 4) * 8;                               // + k0
    int b_row = (lane & 7) + ((lane >> 3) & 1) * 8;            // + k0
    int b_col = wn * 64 + (lane >> 4) * 8;                     // + j*16

#pragma unroll
    for (int kc = 0; kc < 8; ++kc) {
        int k0 = kc * 16;
        uint32_t afr[2][4];
#pragma unroll
        for (int mt = 0; mt < 2; ++mt) {
            uint32_t addr = As_base + (uint32_t)(((a_row + mt * 16) * APAD) + k0 + a_col) * 2u;
            ldsm_x4(afr[mt], addr);
        }
        uint32_t bfr[8][2];
#pragma unroll
        for (int j = 0; j < 4; ++j) {
            uint32_t r[4];
            uint32_t addr = Bs_base + (uint32_t)(((b_row + k0) * APAD) + b_col + j * 16) * 2u;
            ldsm_x4_t(r, addr);
            bfr[2 * j][0] = r[0]; bfr[2 * j][1] = r[1];
            bfr[2 * j + 1][0] = r[2]; bfr[2 * j + 1][1] = r[3];
        }
#pragma unroll
        for (int mt = 0; mt < 2; ++mt)
#pragma unroll
            for (int nt = 0; nt < 8; ++nt)
                mma16816(acc[mt][nt], afr[mt], bfr[nt]);
    }

    // ---- epilogue: write fp16 payload directly from C frags ----
#pragma unroll
    for (int mt = 0; mt < 2; ++mt) {
        int grow0 = rowBase + wm * 32 + mt * 16 + (lane >> 2);
#pragma unroll
        for (int nt = 0; nt < 8; ++nt) {
            int cidx = wn * 32 + nt * 4 + (lane & 3);   // u32 (col-pair) index
            if (grow0 < N_NODES) {
                __half2 p = __floats2half2_rn(acc[mt][nt][0], acc[mt][nt][1]);
                g_hW2[grow0 * 64 + cidx] = *(unsigned*)&p;
            }
            if (grow0 + 8 < N_NODES) {
                __half2 p = __floats2half2_rn(acc[mt][nt][2], acc[mt][nt][3]);
                g_hW2[(grow0 + 8) * 64 + cidx] = *(unsigned*)&p;
            }
        }
    }
}

// ---------------- aggregate (fp16 gather) + fused BN stats ----------------
__global__ __launch_bounds__(256) void agg_kernel(const float* __restrict__ b, int layer) {
    __shared__ float ss[8][HID];
    __shared__ float sq[8][HID];
    int warp = (blockIdx.x * blockDim.x + threadIdx.x) >> 5;
    int w = (threadIdx.x >> 5);
    int lane = threadIdx.x & 31;
    const uint2* hw = (const uint2*)g_hW2;
    float4 acc = make_float4(0, 0, 0, 0);
    if (warp < N_NODES) {
        int e0 = g_rowptr[warp], e1 = g_rowptr[warp + 1];
        int s = 0; float c = 0.0f;
        if (e0 < e1) { s = g_esrc[e0]; c = g_ecoef[e0]; }
        for (int e = e0; e < e1; ++e) {
            int sn = 0; float cn = 0.0f;
            if (e + 1 < e1) { sn = g_esrc[e + 1]; cn = g_ecoef[e + 1]; }
            uint2 u = hw[s * 32 + lane];
            float2 f0 = __half22float2(*(__half2*)&u.x);
            float2 f1 = __half22float2(*(__half2*)&u.y);
            acc.x += c * f0.x; acc.y += c * f0.y;
            acc.z += c * f1.x; acc.w += c * f1.y;
            s = sn; c = cn;
        }
        float di = g_dinv[warp];
        float d2 = di * di;
        uint2 u = hw[warp * 32 + lane];
        float2 f0 = __half22float2(*(__half2*)&u.x);
        float2 f1 = __half22float2(*(__half2*)&u.y);
        acc.x += d2 * f0.x; acc.y += d2 * f0.y;
        acc.z += d2 * f1.x; acc.w += d2 * f1.y;
        float4 bb = ((const float4*)b)[lane];
        acc.x += bb.x; acc.y += bb.y; acc.z += bb.z; acc.w += bb.w;
        ((float4*)g_z)[warp * NH4 + lane] = acc;
    }
    float4 a2 = make_float4(acc.x * acc.x, acc.y * acc.y, acc.z * acc.z, acc.w * acc.w);
    *(float4*)&ss[w][lane * 4] = acc;
    *(float4*)&sq[w][lane * 4] = a2;
    __syncthreads();
    int t = threadIdx.x;
    int arr = t >> 7;
    int c = t & 127;
    const float* base = (arr == 0) ? &ss[0][0] : &sq[0][0];
    float total = 0.0f;
#pragma unroll
    for (int ww = 0; ww < 8; ++ww) total += base[ww * HID + c];
    atomicAdd(&g_stats[layer * 2 * HID + arr * HID + c], total);
}

__global__ __launch_bounds__(128) void bnprep_kernel(const float* __restrict__ gam,
                                                     const float* __restrict__ bet, int layer) {
    int c = threadIdx.x;
    const float* st = &g_stats[layer * 2 * HID];
    const float invN = 1.0f / (float)N_NODES;
    float mu = st[c] * invN;
    float var = st[HID + c] * invN - mu * mu;
    float sc = gam[c] * rsqrtf(var + BN_EPS);
    g_scale[c] = sc;
    g_shift[c] = bet[c] - mu * sc;
}

__device__ __forceinline__ void pool_flush(int g, int lane, float4 s, float4 m, int cnt) {
    int base = g * HID + lane * 4;
    atomicAdd(&g_psum[base + 0], s.x);
    atomicAdd(&g_psum[base + 1], s.y);
    atomicAdd(&g_psum[base + 2], s.z);
    atomicAdd(&g_psum[base + 3], s.w);
    atomicMax(&g_pmax[base + 0], __float_as_uint(m.x));
    atomicMax(&g_pmax[base + 1], __float_as_uint(m.y));
    atomicMax(&g_pmax[base + 2], __float_as_uint(m.z));
    atomicMax(&g_pmax[base + 3], __float_as_uint(m.w));
    if (lane == 0) atomicAdd(&g_pcnt[g], cnt);
}

// pool with fused layer-3 BN + residual + relu: h3 = relu(z*sc+sh + h2)
__global__ __launch_bounds__(256) void pool_kernel(const int* __restrict__ batch) {
    const int NPW = 16;
    int warp = (blockIdx.x * blockDim.x + threadIdx.x) >> 5;
    int lane = threadIdx.x & 31;
    int n0 = warp * NPW;
    if (n0 >= N_NODES) return;
    int n1 = min(n0 + NPW, N_NODES);
    const float4* z4 = (const float4*)g_z;
    const float4* r4 = (const float4*)g_hB;
    float4 sc = *(const float4*)&g_scale[lane * 4];
    float4 sh = *(const float4*)&g_shift[lane * 4];
    float4 sacc = make_float4(0, 0, 0, 0);
    float4 macc = make_float4(0, 0, 0, 0);
    int cur = batch[n0];
    int cnt = 0;
    for (int n = n0; n < n1; ++n) {
        int g = batch[n];
        if (g != cur) {
            pool_flush(cur, lane, sacc, macc, cnt);
            sacc = make_float4(0, 0, 0, 0);
            macc = make_float4(0, 0, 0, 0);
            cnt = 0; cur = g;
        }
        float4 z = z4[n * NH4 + lane];
        float4 r = r4[n * NH4 + lane];
        float4 v;
        v.x = fmaxf(z.x * sc.x + sh.x + r.x, 0.0f);
        v.y = fmaxf(z.y * sc.y + sh.y + r.y, 0.0f);
        v.z = fmaxf(z.z * sc.z + sh.z + r.z, 0.0f);
        v.w = fmaxf(z.w * sc.w + sh.w + r.w, 0.0f);
        sacc.x += v.x; sacc.y += v.y; sacc.z += v.z; sacc.w += v.w;
        macc.x = fmaxf(macc.x, v.x); macc.y = fmaxf(macc.y, v.y);
        macc.z = fmaxf(macc.z, v.z); macc.w = fmaxf(macc.w, v.w);
        ++cnt;
    }
    pool_flush(cur, lane, sacc, macc, cnt);
}

__global__ __launch_bounds__(64) void head_kernel(const float* __restrict__ Wh,
                                                  const float* __restrict__ bh,
                                                  float* __restrict__ out) {
    int g = blockIdx.x;
    int c = threadIdx.x;
    float cntf = (float)g_pcnt[g];
    float inv = 1.0f / fmaxf(cntf, 1.0f);
    float acc = bh[c];
    for (int k = 0; k < HID; ++k) {
        float s = g_psum[g * HID + k];
        float m = s * inv;
        float mx = __uint_as_float(g_pmax[g * HID + k]);
        acc += m * Wh[k * N_CLASSES + c]
             + s * Wh[(HID + k) * N_CLASSES + c]
             + mx * Wh[(2 * HID + k) * N_CLASSES + c];
    }
    out[g * N_CLASSES + c] = acc;
}

// ---------------- launch ----------------
extern "C" void kernel_launch(void* const* d_in, const int* in_sizes, int n_in,
                              void* d_out, int out_size) {
    const float* x    = (const float*)d_in[0];
    const int*   ei   = (const int*)d_in[1];
    const int*   src  = ei;
    const int*   dst  = ei + N_EDGES;
    const int*   batch = (const int*)d_in[2];
    const float* W1 = (const float*)d_in[3];
    const float* b1 = (const float*)d_in[4];
    const float* g1 = (const float*)d_in[5];
    const float* be1 = (const float*)d_in[6];
    const float* W2 = (const float*)d_in[7];
    const float* b2 = (const float*)d_in[8];
    const float* g2 = (const float*)d_in[9];
    const float* be2 = (const float*)d_in[10];
    const float* W3 = (const float*)d_in[11];
    const float* b3 = (const float*)d_in[12];
    const float* g3 = (const float*)d_in[13];
    const float* be3 = (const float*)d_in[14];
    const float* Wh = (const float*)d_in[15];
    const float* bh = (const float*)d_in[16];
    float* out = (float*)d_out;

    cudaFuncSetAttribute(mma_kernel, cudaFuncAttributeMaxDynamicSharedMemorySize,
                         SMEM_MMA_BYTES);

    const int TB = 256;
    const int edgeBlocks = (N_EDGES + TB - 1) / TB;
    const int nodeBlocks = (N_NODES + TB - 1) / TB;
    const int aggBlocks = (N_NODES + 7) / 8;
    const int poolWarps = (N_NODES + 15) / 16;
    const int poolBlocks = (poolWarps * 32 + TB - 1) / TB;

    zero_kernel<<<256, TB>>>();
    hist_kernel<<<edgeBlocks, TB>>>(dst);
    dinv_kernel<<<nodeBlocks, TB>>>();
    scanA_kernel<<<SCAN_NB, 256>>>();
    scanB_kernel<<<1, 512>>>();
    scanC_kernel<<<nodeBlocks, TB>>>();
    scatter_kernel<<<edgeBlocks, TB>>>(src, dst);

    // layer 1: A = x (raw)
    mma_kernel<<<MMA_BLOCKS, 256, SMEM_MMA_BYTES>>>(x, W1, 0);
    agg_kernel<<<aggBlocks, TB>>>(b1, 0);
    bnprep_kernel<<<1, 128>>>(g1, be1, 0);

    // layer 2: A = h1 = relu(bn1(z1)), h1 -> g_hA
    mma_kernel<<<MMA_BLOCKS, 256, SMEM_MMA_BYTES>>>(nullptr, W2, 1);
    agg_kernel<<<aggBlocks, TB>>>(b2, 1);
    bnprep_kernel<<<1, 128>>>(g2, be2, 1);

    // layer 3: A = h2 = relu(bn2(z2) + h1), h2 -> g_hB
    mma_kernel<<<MMA_BLOCKS, 256, SMEM_MMA_BYTES>>>(nullptr, W3, 2);
    agg_kernel<<<aggBlocks, TB>>>(b3, 2);
    bnprep_kernel<<<1, 128>>>(g3, be3, 2);

    // pool (fused bn3 + residual h2) + head
    pool_kernel<<<poolBlocks, TB>>>(batch);
    head_kernel<<<N_GRAPHS, N_CLASSES>>>(Wh, bh, out);
}

// round 8
// speedup vs baseline: 1.5200x; 1.0531x over previous
#include <cuda_runtime.h>
#include <cuda_fp16.h>
#include <cstdint>

#define N_NODES 100000
#define N_EDGES 1600000
#define HID 128
#define NH4 (HID/4)
#define N_GRAPHS 512
#define N_CLASSES 64
#define BN_EPS 1e-5f
#define SCAN_NB 391   // ceil(N_NODES/256)

#define TILE_M 128
#define MMA_BLOCKS ((N_NODES + TILE_M - 1) / TILE_M)   // 782
#define APAD 136                                        // halves per smem row
#define SMEM_MMA_BYTES (2 * 128 * APAD * 2)             // A + B fp16 tiles = 69632

// ---------------- scratch (device globals; allocation-free) ----------------
__device__ __align__(16) unsigned g_hW2[N_NODES * 64]; // h @ W payload, half2 per u32
__device__ float g_z [N_NODES * HID];   // pre-BN conv output
__device__ float g_hA[N_NODES * HID];   // h1
__device__ float g_hB[N_NODES * HID];   // h2
__device__ float g_dinv[N_NODES];
__device__ int   g_cnt[N_NODES];
__device__ int   g_rowptr[N_NODES + 1]; // intra-block partial prefix (+ g_boff[i>>8] = final)
__device__ int   g_cursor[N_NODES];
__device__ int   g_bsum[SCAN_NB];
__device__ int   g_boff[SCAN_NB];
__device__ uint2 g_epair[N_EDGES];      // .x = src node, .y = coef bits
__device__ float g_stats[3 * 2 * HID];
__device__ float g_psum[N_GRAPHS * HID];
__device__ unsigned g_pmax[N_GRAPHS * HID];
__device__ int   g_pcnt[N_GRAPHS];

// ---------------- warp-MMA helpers ----------------
__device__ __forceinline__ uint32_t smem_u32(const void* p) {
    uint32_t a;
    asm("{ .reg .u64 t; cvta.to.shared.u64 t, %1; cvt.u32.u64 %0, t; }" : "=r"(a) : "l"(p));
    return a;
}
__device__ __forceinline__ void ldsm_x4(uint32_t* r, uint32_t addr) {
    asm volatile("ldmatrix.sync.aligned.m8n8.x4.shared.b16 {%0,%1,%2,%3}, [%4];"
                 : "=r"(r[0]), "=r"(r[1]), "=r"(r[2]), "=r"(r[3]) : "r"(addr));
}
__device__ __forceinline__ void ldsm_x4_t(uint32_t* r, uint32_t addr) {
    asm volatile("ldmatrix.sync.aligned.m8n8.x4.trans.shared.b16 {%0,%1,%2,%3}, [%4];"
                 : "=r"(r[0]), "=r"(r[1]), "=r"(r[2]), "=r"(r[3]) : "r"(addr));
}
__device__ __forceinline__ void mma16816(float* c, const uint32_t* a, const uint32_t* b) {
    asm volatile(
        "mma.sync.aligned.m16n8k16.row.col.f32.f16.f16.f32 "
        "{%0,%1,%2,%3}, {%4,%5,%6,%7}, {%8,%9}, {%0,%1,%2,%3};"
        : "+f"(c[0]), "+f"(c[1]), "+f"(c[2]), "+f"(c[3])
        : "r"(a[0]), "r"(a[1]), "r"(a[2]), "r"(a[3]), "r"(b[0]), "r"(b[1]));
}

// ---------------- setup kernels ----------------

__global__ __launch_bounds__(256) void zero_kernel() {
    int i = blockIdx.x * blockDim.x + threadIdx.x;
    int stride = gridDim.x * blockDim.x;
    for (int j = i; j < N_NODES; j += stride) { g_cnt[j] = 0; g_cursor[j] = 0; }
    for (int j = i; j < 3 * 2 * HID; j += stride) g_stats[j] = 0.0f;
    for (int j = i; j < N_GRAPHS * HID; j += stride) { g_psum[j] = 0.0f; g_pmax[j] = 0u; }
    for (int j = i; j < N_GRAPHS; j += stride) g_pcnt[j] = 0;
}

__global__ __launch_bounds__(256) void hist_kernel(const int* __restrict__ dst) {
    int e = blockIdx.x * blockDim.x + threadIdx.x;
    if (e < N_EDGES) atomicAdd(&g_cnt[dst[e]], 1);
}

// per-block partial scan of g_cnt -> g_rowptr, block totals -> g_bsum, dinv folded in
__global__ __launch_bounds__(256) void scanA_kernel() {
    int t = threadIdx.x, b = blockIdx.x;
    int i = b * 256 + t;
    int v = (i < N_NODES) ? g_cnt[i] : 0;
    if (i < N_NODES) g_dinv[i] = rsqrtf((float)v + 1.0f);
    int x = v;
#pragma unroll
    for (int o = 1; o < 32; o <<= 1) {
        int y = __shfl_up_sync(0xffffffffu, x, o);
        if ((t & 31) >= o) x += y;
    }
    __shared__ int wsum[8];
    if ((t & 31) == 31) wsum[t >> 5] = x;
    __syncthreads();
    if (t < 32) {
        int s = (t < 8) ? wsum[t] : 0;
#pragma unroll
        for (int o = 1; o < 8; o <<= 1) {
            int y = __shfl_up_sync(0xffffffffu, s, o);
            if (t >= o) s += y;
        }
        if (t < 8) wsum[t] = s;
    }
    __syncthreads();
    int warpoff = (t >= 32) ? wsum[(t >> 5) - 1] : 0;
    int incl = x + warpoff;
    if (i < N_NODES) g_rowptr[i] = incl - v;  // intra-block exclusive (partial)
    if (t == 255) g_bsum[b] = incl;
}

// scan of block sums -> g_boff; rowptr[N] stays in partial convention
__global__ __launch_bounds__(512) void scanB_kernel() {
    __shared__ int sh[512];
    int t = threadIdx.x;
    int v = (t < SCAN_NB) ? g_bsum[t] : 0;
    sh[t] = v;
    __syncthreads();
    for (int o = 1; o < 512; o <<= 1) {
        int y = (t >= o) ? sh[t - o] : 0;
        __syncthreads();
        sh[t] += y;
        __syncthreads();
    }
    if (t < SCAN_NB) g_boff[t] = sh[t] - v;
    // rowptr[N_NODES] + boff[N_NODES>>8] must equal total: rowptr[N] = bsum[last]
    if (t == SCAN_NB - 1) g_rowptr[N_NODES] = v;
}

__global__ __launch_bounds__(256) void scatter_kernel(const int* __restrict__ src,
                                                      const int* __restrict__ dst) {
    int e = blockIdx.x * blockDim.x + threadIdx.x;
    if (e >= N_EDGES) return;
    int d = dst[e], s = src[e];
    int pos = g_rowptr[d] + g_boff[d >> 8] + atomicAdd(&g_cursor[d], 1);
    uint2 p;
    p.x = (unsigned)s;
    p.y = __float_as_uint(g_dinv[s] * g_dinv[d]);
    g_epair[pos] = p;
}

// ---------------- HMMA GEMM: C = A @ W -> g_hW2 (fp16 payload) ----------------
// mode 0: A = Aext (x). mode 1: A = relu(bn(g_z)), h -> g_hA.
// mode 2: A = relu(bn(g_z) + g_hA), h -> g_hB.
// BN scale/shift computed in-block from g_stats[statIdx] + gam/bet.
__global__ __launch_bounds__(256) void mma_kernel(const float* __restrict__ Aext,
                                                  const float* __restrict__ W,
                                                  const float* __restrict__ gam,
                                                  const float* __restrict__ bet,
                                                  int statIdx, int mode) {
    extern __shared__ __align__(16) __half smh[];
    __half* As = smh;                  // [128][APAD]  rows = m, cols = k
    __half* Bs = smh + 128 * APAD;     // [128][APAD]  rows = k, cols = n
    __shared__ __align__(16) float s_sc[HID];
    __shared__ __align__(16) float s_sh[HID];
    const float* Ain = (mode == 0) ? Aext : g_z;
    const float* res = (mode == 2) ? g_hA : nullptr;
    float* hout = (mode == 1) ? g_hA : ((mode == 2) ? g_hB : nullptr);

    int tid = threadIdx.x;
    int lane = tid & 31, wid = tid >> 5;
    int rowBase = blockIdx.x * TILE_M;

    if (mode != 0) {
        if (tid < HID) {
            const float* st = &g_stats[statIdx * 2 * HID];
            const float invN = 1.0f / (float)N_NODES;
            float mu = st[tid] * invN;
            float var = st[HID + tid] * invN - mu * mu;
            float scv = gam[tid] * rsqrtf(var + BN_EPS);
            s_sc[tid] = scv;
            s_sh[tid] = bet[tid] - mu * scv;
        }
        __syncthreads();
    }

    // ---- stage A (BN fusion) and B = W, both fp16 ----
    {
        int r = tid >> 1;            // 0..127
        int hf = (tid & 1) * 64;     // half-row offset
        int row = rowBase + r;
        bool valid = row < N_NODES;
#pragma unroll
        for (int cc = 0; cc < 8; ++cc) {
            int c = hf + cc * 8;
            float4 v0 = make_float4(0, 0, 0, 0), v1 = make_float4(0, 0, 0, 0);
            if (valid) {
                v0 = *(const float4*)&Ain[row * 128 + c];
                v1 = *(const float4*)&Ain[row * 128 + c + 4];
                if (mode != 0) {
                    float4 s0 = *(const float4*)&s_sc[c];
                    float4 s1 = *(const float4*)&s_sc[c + 4];
                    float4 h0 = *(const float4*)&s_sh[c];
                    float4 h1 = *(const float4*)&s_sh[c + 4];
                    v0.x = v0.x * s0.x + h0.x; v0.y = v0.y * s0.y + h0.y;
                    v0.z = v0.z * s0.z + h0.z; v0.w = v0.w * s0.w + h0.w;
                    v1.x = v1.x * s1.x + h1.x; v1.y = v1.y * s1.y + h1.y;
                    v1.z = v1.z * s1.z + h1.z; v1.w = v1.w * s1.w + h1.w;
                    if (mode == 2) {
                        float4 r0 = *(const float4*)&res[row * 128 + c];
                        float4 r1 = *(const float4*)&res[row * 128 + c + 4];
                        v0.x += r0.x; v0.y += r0.y; v0.z += r0.z; v0.w += r0.w;
                        v1.x += r1.x; v1.y += r1.y; v1.z += r1.z; v1.w += r1.w;
                    }
                    v0.x = fmaxf(v0.x, 0.0f); v0.y = fmaxf(v0.y, 0.0f);
                    v0.z = fmaxf(v0.z, 0.0f); v0.w = fmaxf(v0.w, 0.0f);
                    v1.x = fmaxf(v1.x, 0.0f); v1.y = fmaxf(v1.y, 0.0f);
                    v1.z = fmaxf(v1.z, 0.0f); v1.w = fmaxf(v1.w, 0.0f);
                    *(float4*)&hout[row * 128 + c] = v0;
                    *(float4*)&hout[row * 128 + c + 4] = v1;
                }
            }
            __half2 p0 = __floats2half2_rn(v0.x, v0.y);
            __half2 p1 = __floats2half2_rn(v0.z, v0.w);
            __half2 p2 = __floats2half2_rn(v1.x, v1.y);
            __half2 p3 = __floats2half2_rn(v1.z, v1.w);
            uint4 u;
            u.x = *(unsigned*)&p0; u.y = *(unsigned*)&p1;
            u.z = *(unsigned*)&p2; u.w = *(unsigned*)&p3;
            *(uint4*)&As[r * APAD + c] = u;

            float4 w0 = *(const float4*)&W[r * 128 + c];
            float4 w1 = *(const float4*)&W[r * 128 + c + 4];
            __half2 q0 = __floats2half2_rn(w0.x, w0.y);
            __half2 q1 = __floats2half2_rn(w0.z, w0.w);
            __half2 q2 = __floats2half2_rn(w1.x, w1.y);
            __half2 q3 = __floats2half2_rn(w1.z, w1.w);
            uint4 uw;
            uw.x = *(unsigned*)&q0; uw.y = *(unsigned*)&q1;
            uw.z = *(unsigned*)&q2; uw.w = *(unsigned*)&q3;
            *(uint4*)&Bs[r * APAD + c] = uw;
        }
    }
    __syncthreads();

    // ---- warp tiles: 4x2 warps, each 32(m) x 64(n) ----
    int wm = wid & 3;
    int wn = wid >> 2;
    float acc[2][8][4];
#pragma unroll
    for (int mt = 0; mt < 2; ++mt)
#pragma unroll
        for (int nt = 0; nt < 8; ++nt)
#pragma unroll
            for (int j = 0; j < 4; ++j) acc[mt][nt][j] = 0.0f;

    uint32_t As_base = smem_u32(As);
    uint32_t Bs_base = smem_u32(Bs);
    int a_row = wm * 32 + (lane & 7) + ((lane >> 3) & 1) * 8;
    int a_col = (lane >> 4) * 8;
    int b_row = (lane & 7) + ((lane >> 3) & 1) * 8;
    int b_col = wn * 64 + (lane >> 4) * 8;

#pragma unroll
    for (int kc = 0; kc < 8; ++kc) {
        int k0 = kc * 16;
        uint32_t afr[2][4];
#pragma unroll
        for (int mt = 0; mt < 2; ++mt) {
            uint32_t addr = As_base + (uint32_t)(((a_row + mt * 16) * APAD) + k0 + a_col) * 2u;
            ldsm_x4(afr[mt], addr);
        }
        uint32_t bfr[8][2];
#pragma unroll
        for (int j = 0; j < 4; ++j) {
            uint32_t r[4];
            uint32_t addr = Bs_base + (uint32_t)(((b_row + k0) * APAD) + b_col + j * 16) * 2u;
            ldsm_x4_t(r, addr);
            bfr[2 * j][0] = r[0]; bfr[2 * j][1] = r[1];
            bfr[2 * j + 1][0] = r[2]; bfr[2 * j + 1][1] = r[3];
        }
#pragma unroll
        for (int mt = 0; mt < 2; ++mt)
#pragma unroll
            for (int nt = 0; nt < 8; ++nt)
                mma16816(acc[mt][nt], afr[mt], bfr[nt]);
    }

#pragma unroll
    for (int mt = 0; mt < 2; ++mt) {
        int grow0 = rowBase + wm * 32 + mt * 16 + (lane >> 2);
#pragma unroll
        for (int nt = 0; nt < 8; ++nt) {
            int cidx = wn * 32 + nt * 4 + (lane & 3);
            if (grow0 < N_NODES) {
                __half2 p = __floats2half2_rn(acc[mt][nt][0], acc[mt][nt][1]);
                g_hW2[grow0 * 64 + cidx] = *(unsigned*)&p;
            }
            if (grow0 + 8 < N_NODES) {
                __half2 p = __floats2half2_rn(acc[mt][nt][2], acc[mt][nt][3]);
                g_hW2[(grow0 + 8) * 64 + cidx] = *(unsigned*)&p;
            }
        }
    }
}

// ---------------- aggregate (MLP-4 fp16 gather) + fused BN stats ----------------
__global__ __launch_bounds__(256) void agg_kernel(const float* __restrict__ b, int layer) {
    __shared__ float ss[8][HID];
    __shared__ float sq[8][HID];
    int warp = (blockIdx.x * blockDim.x + threadIdx.x) >> 5;
    int w = (threadIdx.x >> 5);
    int lane = threadIdx.x & 31;
    const uint2* hw = (const uint2*)g_hW2;
    float4 acc = make_float4(0, 0, 0, 0);
    if (warp < N_NODES) {
        int e0 = g_rowptr[warp] + g_boff[warp >> 8];
        int e1 = g_rowptr[warp + 1] + g_boff[(warp + 1) >> 8];
        int e = e0;
        int efull = e0 + ((e1 - e0) & ~3);
        for (; e < efull; e += 4) {
            uint2 p0 = g_epair[e];
            uint2 p1 = g_epair[e + 1];
            uint2 p2 = g_epair[e + 2];
            uint2 p3 = g_epair[e + 3];
            uint2 u0 = hw[(int)p0.x * 32 + lane];
            uint2 u1 = hw[(int)p1.x * 32 + lane];
            uint2 u2 = hw[(int)p2.x * 32 + lane];
            uint2 u3 = hw[(int)p3.x * 32 + lane];
            float c0 = __uint_as_float(p0.y);
            float c1 = __uint_as_float(p1.y);
            float c2 = __uint_as_float(p2.y);
            float c3 = __uint_as_float(p3.y);
            float2 f;
            f = __half22float2(*(__half2*)&u0.x); acc.x += c0 * f.x; acc.y += c0 * f.y;
            f = __half22float2(*(__half2*)&u0.y); acc.z += c0 * f.x; acc.w += c0 * f.y;
            f = __half22float2(*(__half2*)&u1.x); acc.x += c1 * f.x; acc.y += c1 * f.y;
            f = __half22float2(*(__half2*)&u1.y); acc.z += c1 * f.x; acc.w += c1 * f.y;
            f = __half22float2(*(__half2*)&u2.x); acc.x += c2 * f.x; acc.y += c2 * f.y;
            f = __half22float2(*(__half2*)&u2.y); acc.z += c2 * f.x; acc.w += c2 * f.y;
            f = __half22float2(*(__half2*)&u3.x); acc.x += c3 * f.x; acc.y += c3 * f.y;
            f = __half22float2(*(__half2*)&u3.y); acc.z += c3 * f.x; acc.w += c3 * f.y;
        }
        for (; e < e1; ++e) {
            uint2 p = g_epair[e];
            uint2 u = hw[(int)p.x * 32 + lane];
            float c = __uint_as_float(p.y);
            float2 f;
            f = __half22float2(*(__half2*)&u.x); acc.x += c * f.x; acc.y += c * f.y;
            f = __half22float2(*(__half2*)&u.y); acc.z += c * f.x; acc.w += c * f.y;
        }
        float di = g_dinv[warp];
        float d2 = di * di;
        uint2 u = hw[warp * 32 + lane];
        float2 f0 = __half22float2(*(__half2*)&u.x);
        float2 f1 = __half22float2(*(__half2*)&u.y);
        acc.x += d2 * f0.x; acc.y += d2 * f0.y;
        acc.z += d2 * f1.x; acc.w += d2 * f1.y;
        float4 bb = ((const float4*)b)[lane];
        acc.x += bb.x; acc.y += bb.y; acc.z += bb.z; acc.w += bb.w;
        ((float4*)g_z)[warp * NH4 + lane] = acc;
    }
    float4 a2 = make_float4(acc.x * acc.x, acc.y * acc.y, acc.z * acc.z, acc.w * acc.w);
    *(float4*)&ss[w][lane * 4] = acc;
    *(float4*)&sq[w][lane * 4] = a2;
    __syncthreads();
    int t = threadIdx.x;
    int arr = t >> 7;
    int c = t & 127;
    const float* base = (arr == 0) ? &ss[0][0] : &sq[0][0];
    float total = 0.0f;
#pragma unroll
    for (int ww = 0; ww < 8; ++ww) total += base[ww * HID + c];
    atomicAdd(&g_stats[layer * 2 * HID + arr * HID + c], total);
}

__device__ __forceinline__ void pool_flush(int g, int lane, float4 s, float4 m, int cnt) {
    int base = g * HID + lane * 4;
    atomicAdd(&g_psum[base + 0], s.x);
    atomicAdd(&g_psum[base + 1], s.y);
    atomicAdd(&g_psum[base + 2], s.z);
    atomicAdd(&g_psum[base + 3], s.w);
    atomicMax(&g_pmax[base + 0], __float_as_uint(m.x));
    atomicMax(&g_pmax[base + 1], __float_as_uint(m.y));
    atomicMax(&g_pmax[base + 2], __float_as_uint(m.z));
    atomicMax(&g_pmax[base + 3], __float_as_uint(m.w));
    if (lane == 0) atomicAdd(&g_pcnt[g], cnt);
}

// pool with fused layer-3 BN + residual + relu (BN computed in-block from g_stats[2])
__global__ __launch_bounds__(256) void pool_kernel(const int* __restrict__ batch,
                                                   const float* __restrict__ gam,
                                                   const float* __restrict__ bet) {
    __shared__ __align__(16) float s_sc[HID];
    __shared__ __align__(16) float s_sh[HID];
    {
        int t = threadIdx.x;
        if (t < HID) {
            const float* st = &g_stats[2 * 2 * HID];
            const float invN = 1.0f / (float)N_NODES;
            float mu = st[t] * invN;
            float var = st[HID + t] * invN - mu * mu;
            float scv = gam[t] * rsqrtf(var + BN_EPS);
            s_sc[t] = scv;
            s_sh[t] = bet[t] - mu * scv;
        }
        __syncthreads();
    }
    const int NPW = 16;
    int warp = (blockIdx.x * blockDim.x + threadIdx.x) >> 5;
    int lane = threadIdx.x & 31;
    int n0 = warp * NPW;
    if (n0 >= N_NODES) return;
    int n1 = min(n0 + NPW, N_NODES);
    const float4* z4 = (const float4*)g_z;
    const float4* r4 = (const float4*)g_hB;
    float4 sc = *(const float4*)&s_sc[lane * 4];
    float4 sh = *(const float4*)&s_sh[lane * 4];
    float4 sacc = make_float4(0, 0, 0, 0);
    float4 macc = make_float4(0, 0, 0, 0);
    int cur = batch[n0];
    int cnt = 0;
    for (int n = n0; n < n1; ++n) {
        int g = batch[n];
        if (g != cur) {
            pool_flush(cur, lane, sacc, macc, cnt);
            sacc = make_float4(0, 0, 0, 0);
            macc = make_float4(0, 0, 0, 0);
            cnt = 0; cur = g;
        }
        float4 z = z4[n * NH4 + lane];
        float4 r = r4[n * NH4 + lane];
        float4 v;
        v.x = fmaxf(z.x * sc.x + sh.x + r.x, 0.0f);
        v.y = fmaxf(z.y * sc.y + sh.y + r.y, 0.0f);
        v.z = fmaxf(z.z * sc.z + sh.z + r.z, 0.0f);
        v.w = fmaxf(z.w * sc.w + sh.w + r.w, 0.0f);
        sacc.x += v.x; sacc.y += v.y; sacc.z += v.z; sacc.w += v.w;
        macc.x = fmaxf(macc.x, v.x); macc.y = fmaxf(macc.y, v.y);
        macc.z = fmaxf(macc.z, v.z); macc.w = fmaxf(macc.w, v.w);
        ++cnt;
    }
    pool_flush(cur, lane, sacc, macc, cnt);
}

__global__ __launch_bounds__(64) void head_kernel(const float* __restrict__ Wh,
                                                  const float* __restrict__ bh,
                                                  float* __restrict__ out) {
    int g = blockIdx.x;
    int c = threadIdx.x;
    float cntf = (float)g_pcnt[g];
    float inv = 1.0f / fmaxf(cntf, 1.0f);
    float acc = bh[c];
    for (int k = 0; k < HID; ++k) {
        float s = g_psum[g * HID + k];
        float m = s * inv;
        float mx = __uint_as_float(g_pmax[g * HID + k]);
        acc += m * Wh[k * N_CLASSES + c]
             + s * Wh[(HID + k) * N_CLASSES + c]
             + mx * Wh[(2 * HID + k) * N_CLASSES + c];
    }
    out[g * N_CLASSES + c] = acc;
}

// ---------------- launch ----------------
extern "C" void kernel_launch(void* const* d_in, const int* in_sizes, int n_in,
                              void* d_out, int out_size) {
    const float* x    = (const float*)d_in[0];
    const int*   ei   = (const int*)d_in[1];
    const int*   src  = ei;
    const int*   dst  = ei + N_EDGES;
    const int*   batch = (const int*)d_in[2];
    const float* W1 = (const float*)d_in[3];
    const float* b1 = (const float*)d_in[4];
    const float* g1 = (const float*)d_in[5];
    const float* be1 = (const float*)d_in[6];
    const float* W2 = (const float*)d_in[7];
    const float* b2 = (const float*)d_in[8];
    const float* g2 = (const float*)d_in[9];
    const float* be2 = (const float*)d_in[10];
    const float* W3 = (const float*)d_in[11];
    const float* b3 = (const float*)d_in[12];
    const float* g3 = (const float*)d_in[13];
    const float* be3 = (const float*)d_in[14];
    const float* Wh = (const float*)d_in[15];
    const float* bh = (const float*)d_in[16];
    float* out = (float*)d_out;

    cudaFuncSetAttribute(mma_kernel, cudaFuncAttributeMaxDynamicSharedMemorySize,
                         SMEM_MMA_BYTES);

    const int TB = 256;
    const int edgeBlocks = (N_EDGES + TB - 1) / TB;
    const int aggBlocks = (N_NODES + 7) / 8;
    const int poolWarps = (N_NODES + 15) / 16;
    const int poolBlocks = (poolWarps * 32 + TB - 1) / TB;

    zero_kernel<<<256, TB>>>();
    hist_kernel<<<edgeBlocks, TB>>>(dst);
    scanA_kernel<<<SCAN_NB, 256>>>();
    scanB_kernel<<<1, 512>>>();
    scatter_kernel<<<edgeBlocks, TB>>>(src, dst);

    // layer 1: A = x (raw)
    mma_kernel<<<MMA_BLOCKS, 256, SMEM_MMA_BYTES>>>(x, W1, nullptr, nullptr, 0, 0);
    agg_kernel<<<aggBlocks, TB>>>(b1, 0);

    // layer 2: A = h1 = relu(bn1(z1)), h1 -> g_hA
    mma_kernel<<<MMA_BLOCKS, 256, SMEM_MMA_BYTES>>>(nullptr, W2, g1, be1, 0, 1);
    agg_kernel<<<aggBlocks, TB>>>(b2, 1);

    // layer 3: A = h2 = relu(bn2(z2) + h1), h2 -> g_hB
    mma_kernel<<<MMA_BLOCKS, 256, SMEM_MMA_BYTES>>>(nullptr, W3, g2, be2, 1, 2);
    agg_kernel<<<aggBlocks, TB>>>(b3, 2);

    // pool (fused bn3 + residual h2) + head
    pool_kernel<<<poolBlocks, TB>>>(batch, g3, be3);
    head_kernel<<<N_GRAPHS, N_CLASSES>>>(Wh, bh, out);
}

// round 9
// speedup vs baseline: 1.7251x; 1.1349x over previous
#include <cuda_runtime.h>
#include <cuda_fp16.h>
#include <cstdint>

#define N_NODES 100000
#define N_EDGES 1600000
#define HID 128
#define NH4 (HID/4)
#define N_GRAPHS 512
#define N_CLASSES 64
#define BN_EPS 1e-5f
#define SCAN_NB 391   // ceil(N_NODES/256)

#define TILE_M 128
#define MMA_BLOCKS ((N_NODES + TILE_M - 1) / TILE_M)   // 782
#define APAD 136                                        // halves per smem row
#define SMEM_MMA_BYTES (2 * 128 * APAD * 2)             // A + B fp16 tiles = 69632

// ---------------- scratch (device globals; allocation-free) ----------------
__device__ __align__(16) unsigned g_hW2[N_NODES * 64]; // h @ W payload, half2 per u32
__device__ __align__(16) unsigned g_z2 [N_NODES * 64]; // pre-BN conv output, fp16
__device__ __align__(16) unsigned g_h1 [N_NODES * 64]; // h1, fp16
__device__ __align__(16) unsigned g_h2 [N_NODES * 64]; // h2, fp16
__device__ float g_dinv[N_NODES];
__device__ int   g_cnt[N_NODES];
__device__ int   g_rowptr[N_NODES + 1]; // intra-block partial prefix (+ g_boff[i>>8])
__device__ int   g_cursor[N_NODES];
__device__ int   g_bsum[SCAN_NB];
__device__ int   g_boff[SCAN_NB];
__device__ uint2 g_epair[N_EDGES];      // .x = src node, .y = coef bits
__device__ float g_stats[3 * 2 * HID];
__device__ float g_psum[N_GRAPHS * HID];
__device__ unsigned g_pmax[N_GRAPHS * HID];
__device__ int   g_pcnt[N_GRAPHS];

// ---------------- warp-MMA helpers ----------------
__device__ __forceinline__ uint32_t smem_u32(const void* p) {
    uint32_t a;
    asm("{ .reg .u64 t; cvta.to.shared.u64 t, %1; cvt.u32.u64 %0, t; }" : "=r"(a) : "l"(p));
    return a;
}
__device__ __forceinline__ void ldsm_x4(uint32_t* r, uint32_t addr) {
    asm volatile("ldmatrix.sync.aligned.m8n8.x4.shared.b16 {%0,%1,%2,%3}, [%4];"
                 : "=r"(r[0]), "=r"(r[1]), "=r"(r[2]), "=r"(r[3]) : "r"(addr));
}
__device__ __forceinline__ void ldsm_x4_t(uint32_t* r, uint32_t addr) {
    asm volatile("ldmatrix.sync.aligned.m8n8.x4.trans.shared.b16 {%0,%1,%2,%3}, [%4];"
                 : "=r"(r[0]), "=r"(r[1]), "=r"(r[2]), "=r"(r[3]) : "r"(addr));
}
__device__ __forceinline__ void mma16816(float* c, const uint32_t* a, const uint32_t* b) {
    asm volatile(
        "mma.sync.aligned.m16n8k16.row.col.f32.f16.f16.f32 "
        "{%0,%1,%2,%3}, {%4,%5,%6,%7}, {%8,%9}, {%0,%1,%2,%3};"
        : "+f"(c[0]), "+f"(c[1]), "+f"(c[2]), "+f"(c[3])
        : "r"(a[0]), "r"(a[1]), "r"(a[2]), "r"(a[3]), "r"(b[0]), "r"(b[1]));
}
__device__ __forceinline__ float2 h2f(unsigned u) {
    return __half22float2(*(__half2*)&u);
}

// ---------------- setup kernels ----------------

__global__ __launch_bounds__(256) void zero_kernel() {
    int i = blockIdx.x * blockDim.x + threadIdx.x;
    int stride = gridDim.x * blockDim.x;
    for (int j = i; j < N_NODES; j += stride) { g_cnt[j] = 0; g_cursor[j] = 0; }
    for (int j = i; j < 3 * 2 * HID; j += stride) g_stats[j] = 0.0f;
    for (int j = i; j < N_GRAPHS * HID; j += stride) { g_psum[j] = 0.0f; g_pmax[j] = 0u; }
    for (int j = i; j < N_GRAPHS; j += stride) g_pcnt[j] = 0;
}

__global__ __launch_bounds__(256) void hist_kernel(const int* __restrict__ dst) {
    int e = blockIdx.x * blockDim.x + threadIdx.x;
    if (e < N_EDGES) atomicAdd(&g_cnt[dst[e]], 1);
}

// per-block partial scan of g_cnt -> g_rowptr, block totals -> g_bsum, dinv folded in
__global__ __launch_bounds__(256) void scanA_kernel() {
    int t = threadIdx.x, b = blockIdx.x;
    int i = b * 256 + t;
    int v = (i < N_NODES) ? g_cnt[i] : 0;
    if (i < N_NODES) g_dinv[i] = rsqrtf((float)v + 1.0f);
    int x = v;
#pragma unroll
    for (int o = 1; o < 32; o <<= 1) {
        int y = __shfl_up_sync(0xffffffffu, x, o);
        if ((t & 31) >= o) x += y;
    }
    __shared__ int wsum[8];
    if ((t & 31) == 31) wsum[t >> 5] = x;
    __syncthreads();
    if (t < 32) {
        int s = (t < 8) ? wsum[t] : 0;
#pragma unroll
        for (int o = 1; o < 8; o <<= 1) {
            int y = __shfl_up_sync(0xffffffffu, s, o);
            if (t >= o) s += y;
        }
        if (t < 8) wsum[t] = s;
    }
    __syncthreads();
    int warpoff = (t >= 32) ? wsum[(t >> 5) - 1] : 0;
    int incl = x + warpoff;
    if (i < N_NODES) g_rowptr[i] = incl - v;
    if (t == 255) g_bsum[b] = incl;
}

__global__ __launch_bounds__(512) void scanB_kernel() {
    __shared__ int sh[512];
    int t = threadIdx.x;
    int v = (t < SCAN_NB) ? g_bsum[t] : 0;
    sh[t] = v;
    __syncthreads();
    for (int o = 1; o < 512; o <<= 1) {
        int y = (t >= o) ? sh[t - o] : 0;
        __syncthreads();
        sh[t] += y;
        __syncthreads();
    }
    if (t < SCAN_NB) g_boff[t] = sh[t] - v;
    if (t == SCAN_NB - 1) g_rowptr[N_NODES] = v;
}

__global__ __launch_bounds__(256) void scatter_kernel(const int* __restrict__ src,
                                                      const int* __restrict__ dst) {
    int e = blockIdx.x * blockDim.x + threadIdx.x;
    if (e >= N_EDGES) return;
    int d = dst[e], s = src[e];
    int pos = g_rowptr[d] + g_boff[d >> 8] + atomicAdd(&g_cursor[d], 1);
    uint2 p;
    p.x = (unsigned)s;
    p.y = __float_as_uint(g_dinv[s] * g_dinv[d]);
    g_epair[pos] = p;
}

// ---------------- HMMA GEMM: C = A @ W -> g_hW2 (fp16 payload) ----------------
// mode 0: A = Aext (x fp32). mode 1: A = relu(bn(g_z2)), h -> g_h1.
// mode 2: A = relu(bn(g_z2) + g_h1), h -> g_h2.
__global__ __launch_bounds__(256) void mma_kernel(const float* __restrict__ Aext,
                                                  const float* __restrict__ W,
                                                  const float* __restrict__ gam,
                                                  const float* __restrict__ bet,
                                                  int statIdx, int mode) {
    extern __shared__ __align__(16) __half smh[];
    __half* As = smh;                  // [128][APAD]
    __half* Bs = smh + 128 * APAD;     // [128][APAD]
    __shared__ __align__(16) float s_sc[HID];
    __shared__ __align__(16) float s_sh[HID];

    int tid = threadIdx.x;
    int lane = tid & 31, wid = tid >> 5;
    int rowBase = blockIdx.x * TILE_M;

    if (mode != 0) {
        if (tid < HID) {
            const float* st = &g_stats[statIdx * 2 * HID];
            const float invN = 1.0f / (float)N_NODES;
            float mu = st[tid] * invN;
            float var = st[HID + tid] * invN - mu * mu;
            float scv = gam[tid] * rsqrtf(var + BN_EPS);
            s_sc[tid] = scv;
            s_sh[tid] = bet[tid] - mu * scv;
        }
        __syncthreads();
    }

    // ---- stage A (fp16 path with BN fusion) and B = W ----
    {
        int r = tid >> 1;            // 0..127
        int hf = (tid & 1) * 64;     // half-row offset
        int row = rowBase + r;
        bool valid = row < N_NODES;
        unsigned* hout = (mode == 1) ? g_h1 : g_h2;
#pragma unroll
        for (int cc = 0; cc < 8; ++cc) {
            int c = hf + cc * 8;
            uint4 u = make_uint4(0, 0, 0, 0);
            if (valid) {
                if (mode == 0) {
                    float4 v0 = *(const float4*)&Aext[row * 128 + c];
                    float4 v1 = *(const float4*)&Aext[row * 128 + c + 4];
                    __half2 p0 = __floats2half2_rn(v0.x, v0.y);
                    __half2 p1 = __floats2half2_rn(v0.z, v0.w);
                    __half2 p2 = __floats2half2_rn(v1.x, v1.y);
                    __half2 p3 = __floats2half2_rn(v1.z, v1.w);
                    u.x = *(unsigned*)&p0; u.y = *(unsigned*)&p1;
                    u.z = *(unsigned*)&p2; u.w = *(unsigned*)&p3;
                } else {
                    uint4 zu = *(const uint4*)&g_z2[row * 64 + (c >> 1)];
                    float2 f0 = h2f(zu.x), f1 = h2f(zu.y), f2 = h2f(zu.z), f3 = h2f(zu.w);
                    float4 s0 = *(const float4*)&s_sc[c];
                    float4 s1 = *(const float4*)&s_sc[c + 4];
                    float4 h0 = *(const float4*)&s_sh[c];
                    float4 h1 = *(const float4*)&s_sh[c + 4];
                    f0.x = f0.x * s0.x + h0.x; f0.y = f0.y * s0.y + h0.y;
                    f1.x = f1.x * s0.z + h0.z; f1.y = f1.y * s0.w + h0.w;
                    f2.x = f2.x * s1.x + h1.x; f2.y = f2.y * s1.y + h1.y;
                    f3.x = f3.x * s1.z + h1.z; f3.y = f3.y * s1.w + h1.w;
                    if (mode == 2) {
                        uint4 ru = *(const uint4*)&g_h1[row * 64 + (c >> 1)];
                        float2 r0 = h2f(ru.x), r1 = h2f(ru.y), r2 = h2f(ru.z), r3 = h2f(ru.w);
                        f0.x += r0.x; f0.y += r0.y;
                        f1.x += r1.x; f1.y += r1.y;
                        f2.x += r2.x; f2.y += r2.y;
                        f3.x += r3.x; f3.y += r3.y;
                    }
                    f0.x = fmaxf(f0.x, 0.0f); f0.y = fmaxf(f0.y, 0.0f);
                    f1.x = fmaxf(f1.x, 0.0f); f1.y = fmaxf(f1.y, 0.0f);
                    f2.x = fmaxf(f2.x, 0.0f); f2.y = fmaxf(f2.y, 0.0f);
                    f3.x = fmaxf(f3.x, 0.0f); f3.y = fmaxf(f3.y, 0.0f);
                    __half2 p0 = __floats2half2_rn(f0.x, f0.y);
                    __half2 p1 = __floats2half2_rn(f1.x, f1.y);
                    __half2 p2 = __floats2half2_rn(f2.x, f2.y);
                    __half2 p3 = __floats2half2_rn(f3.x, f3.y);
                    u.x = *(unsigned*)&p0; u.y = *(unsigned*)&p1;
                    u.z = *(unsigned*)&p2; u.w = *(unsigned*)&p3;
                    *(uint4*)&hout[row * 64 + (c >> 1)] = u;
                }
            }
            *(uint4*)&As[r * APAD + c] = u;

            float4 w0 = *(const float4*)&W[r * 128 + c];
            float4 w1 = *(const float4*)&W[r * 128 + c + 4];
            __half2 q0 = __floats2half2_rn(w0.x, w0.y);
            __half2 q1 = __floats2half2_rn(w0.z, w0.w);
            __half2 q2 = __floats2half2_rn(w1.x, w1.y);
            __half2 q3 = __floats2half2_rn(w1.z, w1.w);
            uint4 uw;
            uw.x = *(unsigned*)&q0; uw.y = *(unsigned*)&q1;
            uw.z = *(unsigned*)&q2; uw.w = *(unsigned*)&q3;
            *(uint4*)&Bs[r * APAD + c] = uw;
        }
    }
    __syncthreads();

    // ---- warp tiles: 4x2 warps, each 32(m) x 64(n) ----
    int wm = wid & 3;
    int wn = wid >> 2;
    float acc[2][8][4];
#pragma unroll
    for (int mt = 0; mt < 2; ++mt)
#pragma unroll
        for (int nt = 0; nt < 8; ++nt)
#pragma unroll
            for (int j = 0; j < 4; ++j) acc[mt][nt][j] = 0.0f;

    uint32_t As_base = smem_u32(As);
    uint32_t Bs_base = smem_u32(Bs);
    int a_row = wm * 32 + (lane & 7) + ((lane >> 3) & 1) * 8;
    int a_col = (lane >> 4) * 8;
    int b_row = (lane & 7) + ((lane >> 3) & 1) * 8;
    int b_col = wn * 64 + (lane >> 4) * 8;

#pragma unroll
    for (int kc = 0; kc < 8; ++kc) {
        int k0 = kc * 16;
        uint32_t afr[2][4];
#pragma unroll
        for (int mt = 0; mt < 2; ++mt) {
            uint32_t addr = As_base + (uint32_t)(((a_row + mt * 16) * APAD) + k0 + a_col) * 2u;
            ldsm_x4(afr[mt], addr);
        }
        uint32_t bfr[8][2];
#pragma unroll
        for (int j = 0; j < 4; ++j) {
            uint32_t r[4];
            uint32_t addr = Bs_base + (uint32_t)(((b_row + k0) * APAD) + b_col + j * 16) * 2u;
            ldsm_x4_t(r, addr);
            bfr[2 * j][0] = r[0]; bfr[2 * j][1] = r[1];
            bfr[2 * j + 1][0] = r[2]; bfr[2 * j + 1][1] = r[3];
        }
#pragma unroll
        for (int mt = 0; mt < 2; ++mt)
#pragma unroll
            for (int nt = 0; nt < 8; ++nt)
                mma16816(acc[mt][nt], afr[mt], bfr[nt]);
    }

#pragma unroll
    for (int mt = 0; mt < 2; ++mt) {
        int grow0 = rowBase + wm * 32 + mt * 16 + (lane >> 2);
#pragma unroll
        for (int nt = 0; nt < 8; ++nt) {
            int cidx = wn * 32 + nt * 4 + (lane & 3);
            if (grow0 < N_NODES) {
                __half2 p = __floats2half2_rn(acc[mt][nt][0], acc[mt][nt][1]);
                g_hW2[grow0 * 64 + cidx] = *(unsigned*)&p;
            }
            if (grow0 + 8 < N_NODES) {
                __half2 p = __floats2half2_rn(acc[mt][nt][2], acc[mt][nt][3]);
                g_hW2[(grow0 + 8) * 64 + cidx] = *(unsigned*)&p;
            }
        }
    }
}

// ---------------- aggregate (MLP-4 fp16 gather) + fused BN stats ----------------
__global__ __launch_bounds__(256) void agg_kernel(const float* __restrict__ b, int layer) {
    __shared__ float ss[8][HID];
    __shared__ float sq[8][HID];
    int warp = (blockIdx.x * blockDim.x + threadIdx.x) >> 5;
    int w = (threadIdx.x >> 5);
    int lane = threadIdx.x & 31;
    const uint2* hw = (const uint2*)g_hW2;
    float4 acc = make_float4(0, 0, 0, 0);
    if (warp < N_NODES) {
        int e0 = g_rowptr[warp] + g_boff[warp >> 8];
        int e1 = g_rowptr[warp + 1] + g_boff[(warp + 1) >> 8];
        int e = e0;
        int efull = e0 + ((e1 - e0) & ~3);
        for (; e < efull; e += 4) {
            uint2 p0 = g_epair[e];
            uint2 p1 = g_epair[e + 1];
            uint2 p2 = g_epair[e + 2];
            uint2 p3 = g_epair[e + 3];
            uint2 u0 = hw[(int)p0.x * 32 + lane];
            uint2 u1 = hw[(int)p1.x * 32 + lane];
            uint2 u2 = hw[(int)p2.x * 32 + lane];
            uint2 u3 = hw[(int)p3.x * 32 + lane];
            float c0 = __uint_as_float(p0.y);
            float c1 = __uint_as_float(p1.y);
            float c2 = __uint_as_float(p2.y);
            float c3 = __uint_as_float(p3.y);
            float2 f;
            f = h2f(u0.x); acc.x += c0 * f.x; acc.y += c0 * f.y;
            f = h2f(u0.y); acc.z += c0 * f.x; acc.w += c0 * f.y;
            f = h2f(u1.x); acc.x += c1 * f.x; acc.y += c1 * f.y;
            f = h2f(u1.y); acc.z += c1 * f.x; acc.w += c1 * f.y;
            f = h2f(u2.x); acc.x += c2 * f.x; acc.y += c2 * f.y;
            f = h2f(u2.y); acc.z += c2 * f.x; acc.w += c2 * f.y;
            f = h2f(u3.x); acc.x += c3 * f.x; acc.y += c3 * f.y;
            f = h2f(u3.y); acc.z += c3 * f.x; acc.w += c3 * f.y;
        }
        for (; e < e1; ++e) {
            uint2 p = g_epair[e];
            uint2 u = hw[(int)p.x * 32 + lane];
            float c = __uint_as_float(p.y);
            float2 f;
            f = h2f(u.x); acc.x += c * f.x; acc.y += c * f.y;
            f = h2f(u.y); acc.z += c * f.x; acc.w += c * f.y;
        }
        float di = g_dinv[warp];
        float d2 = di * di;
        uint2 u = hw[warp * 32 + lane];
        float2 f0 = h2f(u.x);
        float2 f1 = h2f(u.y);
        acc.x += d2 * f0.x; acc.y += d2 * f0.y;
        acc.z += d2 * f1.x; acc.w += d2 * f1.y;
        float4 bb = ((const float4*)b)[lane];
        acc.x += bb.x; acc.y += bb.y; acc.z += bb.z; acc.w += bb.w;
        // store z fp16
        __half2 za = __floats2half2_rn(acc.x, acc.y);
        __half2 zb = __floats2half2_rn(acc.z, acc.w);
        uint2 zo;
        zo.x = *(unsigned*)&za; zo.y = *(unsigned*)&zb;
        ((uint2*)g_z2)[warp * 32 + lane] = zo;
    }
    float4 a2 = make_float4(acc.x * acc.x, acc.y * acc.y, acc.z * acc.z, acc.w * acc.w);
    *(float4*)&ss[w][lane * 4] = acc;
    *(float4*)&sq[w][lane * 4] = a2;
    __syncthreads();
    int t = threadIdx.x;
    int arr = t >> 7;
    int c = t & 127;
    const float* base = (arr == 0) ? &ss[0][0] : &sq[0][0];
    float total = 0.0f;
#pragma unroll
    for (int ww = 0; ww < 8; ++ww) total += base[ww * HID + c];
    atomicAdd(&g_stats[layer * 2 * HID + arr * HID + c], total);
}

__device__ __forceinline__ void pool_flush(int g, int lane, float4 s, float4 m, int cnt) {
    int base = g * HID + lane * 4;
    atomicAdd(&g_psum[base + 0], s.x);
    atomicAdd(&g_psum[base + 1], s.y);
    atomicAdd(&g_psum[base + 2], s.z);
    atomicAdd(&g_psum[base + 3], s.w);
    atomicMax(&g_pmax[base + 0], __float_as_uint(m.x));
    atomicMax(&g_pmax[base + 1], __float_as_uint(m.y));
    atomicMax(&g_pmax[base + 2], __float_as_uint(m.z));
    atomicMax(&g_pmax[base + 3], __float_as_uint(m.w));
    if (lane == 0) atomicAdd(&g_pcnt[g], cnt);
}

// pool with fused layer-3 BN + residual + relu (BN from g_stats[2]); fp16 inputs
__global__ __launch_bounds__(256) void pool_kernel(const int* __restrict__ batch,
                                                   const float* __restrict__ gam,
                                                   const float* __restrict__ bet) {
    __shared__ __align__(16) float s_sc[HID];
    __shared__ __align__(16) float s_sh[HID];
    {
        int t = threadIdx.x;
        if (t < HID) {
            const float* st = &g_stats[2 * 2 * HID];
            const float invN = 1.0f / (float)N_NODES;
            float mu = st[t] * invN;
            float var = st[HID + t] * invN - mu * mu;
            float scv = gam[t] * rsqrtf(var + BN_EPS);
            s_sc[t] = scv;
            s_sh[t] = bet[t] - mu * scv;
        }
        __syncthreads();
    }
    const int NPW = 16;
    int warp = (blockIdx.x * blockDim.x + threadIdx.x) >> 5;
    int lane = threadIdx.x & 31;
    int n0 = warp * NPW;
    if (n0 >= N_NODES) return;
    int n1 = min(n0 + NPW, N_NODES);
    const uint2* z2 = (const uint2*)g_z2;
    const uint2* r2 = (const uint2*)g_h2;
    float4 sc = *(const float4*)&s_sc[lane * 4];
    float4 sh = *(const float4*)&s_sh[lane * 4];
    float4 sacc = make_float4(0, 0, 0, 0);
    float4 macc = make_float4(0, 0, 0, 0);
    int cur = batch[n0];
    int cnt = 0;
    for (int n = n0; n < n1; ++n) {
        int g = batch[n];
        if (g != cur) {
            pool_flush(cur, lane, sacc, macc, cnt);
            sacc = make_float4(0, 0, 0, 0);
            macc = make_float4(0, 0, 0, 0);
            cnt = 0; cur = g;
        }
        uint2 zu = z2[n * 32 + lane];
        uint2 ru = r2[n * 32 + lane];
        float2 z0 = h2f(zu.x), z1 = h2f(zu.y);
        float2 r0 = h2f(ru.x), r1 = h2f(ru.y);
        float4 v;
        v.x = fmaxf(z0.x * sc.x + sh.x + r0.x, 0.0f);
        v.y = fmaxf(z0.y * sc.y + sh.y + r0.y, 0.0f);
        v.z = fmaxf(z1.x * sc.z + sh.z + r1.x, 0.0f);
        v.w = fmaxf(z1.y * sc.w + sh.w + r1.y, 0.0f);
        sacc.x += v.x; sacc.y += v.y; sacc.z += v.z; sacc.w += v.w;
        macc.x = fmaxf(macc.x, v.x); macc.y = fmaxf(macc.y, v.y);
        macc.z = fmaxf(macc.z, v.z); macc.w = fmaxf(macc.w, v.w);
        ++cnt;
    }
    pool_flush(cur, lane, sacc, macc, cnt);
}

__global__ __launch_bounds__(64) void head_kernel(const float* __restrict__ Wh,
                                                  const float* __restrict__ bh,
                                                  float* __restrict__ out) {
    int g = blockIdx.x;
    int c = threadIdx.x;
    float cntf = (float)g_pcnt[g];
    float inv = 1.0f / fmaxf(cntf, 1.0f);
    float acc = bh[c];
    for (int k = 0; k < HID; ++k) {
        float s = g_psum[g * HID + k];
        float m = s * inv;
        float mx = __uint_as_float(g_pmax[g * HID + k]);
        acc += m * Wh[k * N_CLASSES + c]
             + s * Wh[(HID + k) * N_CLASSES + c]
             + mx * Wh[(2 * HID + k) * N_CLASSES + c];
    }
    out[g * N_CLASSES + c] = acc;
}

// ---------------- launch ----------------
extern "C" void kernel_launch(void* const* d_in, const int* in_sizes, int n_in,
                              void* d_out, int out_size) {
    const float* x    = (const float*)d_in[0];
    const int*   ei   = (const int*)d_in[1];
    const int*   src  = ei;
    const int*   dst  = ei + N_EDGES;
    const int*   batch = (const int*)d_in[2];
    const float* W1 = (const float*)d_in[3];
    const float* b1 = (const float*)d_in[4];
    const float* g1 = (const float*)d_in[5];
    const float* be1 = (const float*)d_in[6];
    const float* W2 = (const float*)d_in[7];
    const float* b2 = (const float*)d_in[8];
    const float* g2 = (const float*)d_in[9];
    const float* be2 = (const float*)d_in[10];
    const float* W3 = (const float*)d_in[11];
    const float* b3 = (const float*)d_in[12];
    const float* g3 = (const float*)d_in[13];
    const float* be3 = (const float*)d_in[14];
    const float* Wh = (const float*)d_in[15];
    const float* bh = (const float*)d_in[16];
    float* out = (float*)d_out;

    cudaFuncSetAttribute(mma_kernel, cudaFuncAttributeMaxDynamicSharedMemorySize,
                         SMEM_MMA_BYTES);

    const int TB = 256;
    const int edgeBlocks = (N_EDGES + TB - 1) / TB;
    const int aggBlocks = (N_NODES + 7) / 8;
    const int poolWarps = (N_NODES + 15) / 16;
    const int poolBlocks = (poolWarps * 32 + TB - 1) / TB;

    zero_kernel<<<256, TB>>>();
    hist_kernel<<<edgeBlocks, TB>>>(dst);
    scanA_kernel<<<SCAN_NB, 256>>>();
    scanB_kernel<<<1, 512>>>();
    scatter_kernel<<<edgeBlocks, TB>>>(src, dst);

    // layer 1: A = x (raw fp32)
    mma_kernel<<<MMA_BLOCKS, 256, SMEM_MMA_BYTES>>>(x, W1, nullptr, nullptr, 0, 0);
    agg_kernel<<<aggBlocks, TB>>>(b1, 0);

    // layer 2: A = h1 = relu(bn1(z1)), h1 -> g_h1
    mma_kernel<<<MMA_BLOCKS, 256, SMEM_MMA_BYTES>>>(nullptr, W2, g1, be1, 0, 1);
    agg_kernel<<<aggBlocks, TB>>>(b2, 1);

    // layer 3: A = h2 = relu(bn2(z2) + h1), h2 -> g_h2
    mma_kernel<<<MMA_BLOCKS, 256, SMEM_MMA_BYTES>>>(nullptr, W3, g2, be2, 1, 2);
    agg_kernel<<<aggBlocks, TB>>>(b3, 2);

    // pool (fused bn3 + residual h2) + head
    pool_kernel<<<poolBlocks, TB>>>(batch, g3, be3);
    head_kernel<<<N_GRAPHS, N_CLASSES>>>(Wh, bh, out);
}

// round 10
// speedup vs baseline: 1.9418x; 1.1256x over previous
#include <cuda_runtime.h>
#include <cuda_fp16.h>
#include <cstdint>

#define N_NODES 100000
#define N_EDGES 1600000
#define HID 128
#define NH4 (HID/4)
#define N_GRAPHS 512
#define N_CLASSES 64
#define BN_EPS 1e-5f
#define SCAN_NB 391   // ceil(N_NODES/256)

#define TILE_M 128
#define MMA_BLOCKS ((N_NODES + TILE_M - 1) / TILE_M)   // 782
#define APAD 136                                        // halves per smem row
#define SMEM_MMA_BYTES (2 * 128 * APAD * 2)             // A + B fp16 tiles = 69632
#define NPWA 4                                          // nodes per warp in agg

// ---------------- scratch (device globals; allocation-free) ----------------
__device__ __align__(16) unsigned g_hW2[N_NODES * 64]; // payload = dinv*h@W, half2/u32
__device__ __align__(16) unsigned g_z2 [N_NODES * 64]; // pre-BN conv output, fp16
__device__ __align__(16) unsigned g_h1 [N_NODES * 64]; // h1, fp16
__device__ __align__(16) unsigned g_h2 [N_NODES * 64]; // h2, fp16
__device__ float g_dinv[N_NODES];
__device__ int   g_cnt[N_NODES];
__device__ int   g_rowptr[N_NODES + 1]; // intra-block partial prefix (+ g_boff[i>>8])
__device__ int   g_cursor[N_NODES];
__device__ int   g_bsum[SCAN_NB];
__device__ int   g_boff[SCAN_NB];
__device__ int   g_esrc[N_EDGES];       // CSR-sorted source node per edge
__device__ float g_stats[3 * 2 * HID];
__device__ float g_psum[N_GRAPHS * HID];
__device__ unsigned g_pmax[N_GRAPHS * HID];
__device__ int   g_pcnt[N_GRAPHS];

// ---------------- warp-MMA helpers ----------------
__device__ __forceinline__ uint32_t smem_u32(const void* p) {
    uint32_t a;
    asm("{ .reg .u64 t; cvta.to.shared.u64 t, %1; cvt.u32.u64 %0, t; }" : "=r"(a) : "l"(p));
    return a;
}
__device__ __forceinline__ void ldsm_x4(uint32_t* r, uint32_t addr) {
    asm volatile("ldmatrix.sync.aligned.m8n8.x4.shared.b16 {%0,%1,%2,%3}, [%4];"
                 : "=r"(r[0]), "=r"(r[1]), "=r"(r[2]), "=r"(r[3]) : "r"(addr));
}
__device__ __forceinline__ void ldsm_x4_t(uint32_t* r, uint32_t addr) {
    asm volatile("ldmatrix.sync.aligned.m8n8.x4.trans.shared.b16 {%0,%1,%2,%3}, [%4];"
                 : "=r"(r[0]), "=r"(r[1]), "=r"(r[2]), "=r"(r[3]) : "r"(addr));
}
__device__ __forceinline__ void mma16816(float* c, const uint32_t* a, const uint32_t* b) {
    asm volatile(
        "mma.sync.aligned.m16n8k16.row.col.f32.f16.f16.f32 "
        "{%0,%1,%2,%3}, {%4,%5,%6,%7}, {%8,%9}, {%0,%1,%2,%3};"
        : "+f"(c[0]), "+f"(c[1]), "+f"(c[2]), "+f"(c[3])
        : "r"(a[0]), "r"(a[1]), "r"(a[2]), "r"(a[3]), "r"(b[0]), "r"(b[1]));
}
__device__ __forceinline__ float2 h2f(unsigned u) {
    return __half22float2(*(__half2*)&u);
}

// ---------------- setup kernels ----------------

__global__ __launch_bounds__(256) void zero_kernel() {
    int i = blockIdx.x * blockDim.x + threadIdx.x;
    int stride = gridDim.x * blockDim.x;
    for (int j = i; j < N_NODES; j += stride) { g_cnt[j] = 0; g_cursor[j] = 0; }
    for (int j = i; j < 3 * 2 * HID; j += stride) g_stats[j] = 0.0f;
    for (int j = i; j < N_GRAPHS * HID; j += stride) { g_psum[j] = 0.0f; g_pmax[j] = 0u; }
    for (int j = i; j < N_GRAPHS; j += stride) g_pcnt[j] = 0;
}

__global__ __launch_bounds__(256) void hist_kernel(const int* __restrict__ dst) {
    int e = blockIdx.x * blockDim.x + threadIdx.x;
    if (e < N_EDGES) atomicAdd(&g_cnt[dst[e]], 1);
}

// per-block partial scan of g_cnt -> g_rowptr, block totals -> g_bsum, dinv folded in
__global__ __launch_bounds__(256) void scanA_kernel() {
    int t = threadIdx.x, b = blockIdx.x;
    int i = b * 256 + t;
    int v = (i < N_NODES) ? g_cnt[i] : 0;
    if (i < N_NODES) g_dinv[i] = rsqrtf((float)v + 1.0f);
    int x = v;
#pragma unroll
    for (int o = 1; o < 32; o <<= 1) {
        int y = __shfl_up_sync(0xffffffffu, x, o);
        if ((t & 31) >= o) x += y;
    }
    __shared__ int wsum[8];
    if ((t & 31) == 31) wsum[t >> 5] = x;
    __syncthreads();
    if (t < 32) {
        int s = (t < 8) ? wsum[t] : 0;
#pragma unroll
        for (int o = 1; o < 8; o <<= 1) {
            int y = __shfl_up_sync(0xffffffffu, s, o);
            if (t >= o) s += y;
        }
        if (t < 8) wsum[t] = s;
    }
    __syncthreads();
    int warpoff = (t >= 32) ? wsum[(t >> 5) - 1] : 0;
    int incl = x + warpoff;
    if (i < N_NODES) g_rowptr[i] = incl - v;
    if (t == 255) g_bsum[b] = incl;
}

__global__ __launch_bounds__(512) void scanB_kernel() {
    __shared__ int sh[512];
    int t = threadIdx.x;
    int v = (t < SCAN_NB) ? g_bsum[t] : 0;
    sh[t] = v;
    __syncthreads();
    for (int o = 1; o < 512; o <<= 1) {
        int y = (t >= o) ? sh[t - o] : 0;
        __syncthreads();
        sh[t] += y;
        __syncthreads();
    }
    if (t < SCAN_NB) g_boff[t] = sh[t] - v;
    if (t == SCAN_NB - 1) g_rowptr[N_NODES] = v;
}

__global__ __launch_bounds__(256) void scatter_kernel(const int* __restrict__ src,
                                                      const int* __restrict__ dst) {
    int e = blockIdx.x * blockDim.x + threadIdx.x;
    if (e >= N_EDGES) return;
    int d = dst[e], s = src[e];
    int pos = g_rowptr[d] + g_boff[d >> 8] + atomicAdd(&g_cursor[d], 1);
    g_esrc[pos] = s;
}

// ---------------- HMMA GEMM: payload = dinv * (A @ W) -> g_hW2 (fp16) ----------------
// mode 0: A = Aext (x fp32). mode 1: A = relu(bn(g_z2)), h -> g_h1.
// mode 2: A = relu(bn(g_z2) + g_h1), h -> g_h2.
__global__ __launch_bounds__(256) void mma_kernel(const float* __restrict__ Aext,
                                                  const float* __restrict__ W,
                                                  const float* __restrict__ gam,
                                                  const float* __restrict__ bet,
                                                  int statIdx, int mode) {
    extern __shared__ __align__(16) __half smh[];
    __half* As = smh;                  // [128][APAD]
    __half* Bs = smh + 128 * APAD;     // [128][APAD]
    __shared__ __align__(16) float s_sc[HID];
    __shared__ __align__(16) float s_sh[HID];

    int tid = threadIdx.x;
    int lane = tid & 31, wid = tid >> 5;
    int rowBase = blockIdx.x * TILE_M;

    if (mode != 0) {
        if (tid < HID) {
            const float* st = &g_stats[statIdx * 2 * HID];
            const float invN = 1.0f / (float)N_NODES;
            float mu = st[tid] * invN;
            float var = st[HID + tid] * invN - mu * mu;
            float scv = gam[tid] * rsqrtf(var + BN_EPS);
            s_sc[tid] = scv;
            s_sh[tid] = bet[tid] - mu * scv;
        }
        __syncthreads();
    }

    // ---- stage A (fp16 path with BN fusion) and B = W ----
    {
        int r = tid >> 1;            // 0..127
        int hf = (tid & 1) * 64;     // half-row offset
        int row = rowBase + r;
        bool valid = row < N_NODES;
        unsigned* hout = (mode == 1) ? g_h1 : g_h2;
#pragma unroll
        for (int cc = 0; cc < 8; ++cc) {
            int c = hf + cc * 8;
            uint4 u = make_uint4(0, 0, 0, 0);
            if (valid) {
                if (mode == 0) {
                    float4 v0 = *(const float4*)&Aext[row * 128 + c];
                    float4 v1 = *(const float4*)&Aext[row * 128 + c + 4];
                    __half2 p0 = __floats2half2_rn(v0.x, v0.y);
                    __half2 p1 = __floats2half2_rn(v0.z, v0.w);
                    __half2 p2 = __floats2half2_rn(v1.x, v1.y);
                    __half2 p3 = __floats2half2_rn(v1.z, v1.w);
                    u.x = *(unsigned*)&p0; u.y = *(unsigned*)&p1;
                    u.z = *(unsigned*)&p2; u.w = *(unsigned*)&p3;
                } else {
                    uint4 zu = *(const uint4*)&g_z2[row * 64 + (c >> 1)];
                    float2 f0 = h2f(zu.x), f1 = h2f(zu.y), f2 = h2f(zu.z), f3 = h2f(zu.w);
                    float4 s0 = *(const float4*)&s_sc[c];
                    float4 s1 = *(const float4*)&s_sc[c + 4];
                    float4 h0 = *(const float4*)&s_sh[c];
                    float4 h1 = *(const float4*)&s_sh[c + 4];
                    f0.x = f0.x * s0.x + h0.x; f0.y = f0.y * s0.y + h0.y;
                    f1.x = f1.x * s0.z + h0.z; f1.y = f1.y * s0.w + h0.w;
                    f2.x = f2.x * s1.x + h1.x; f2.y = f2.y * s1.y + h1.y;
                    f3.x = f3.x * s1.z + h1.z; f3.y = f3.y * s1.w + h1.w;
                    if (mode == 2) {
                        uint4 ru = *(const uint4*)&g_h1[row * 64 + (c >> 1)];
                        float2 r0 = h2f(ru.x), r1 = h2f(ru.y), r2 = h2f(ru.z), r3 = h2f(ru.w);
                        f0.x += r0.x; f0.y += r0.y;
                        f1.x += r1.x; f1.y += r1.y;
                        f2.x += r2.x; f2.y += r2.y;
                        f3.x += r3.x; f3.y += r3.y;
                    }
                    f0.x = fmaxf(f0.x, 0.0f); f0.y = fmaxf(f0.y, 0.0f);
                    f1.x = fmaxf(f1.x, 0.0f); f1.y = fmaxf(f1.y, 0.0f);
                    f2.x = fmaxf(f2.x, 0.0f); f2.y = fmaxf(f2.y, 0.0f);
                    f3.x = fmaxf(f3.x, 0.0f); f3.y = fmaxf(f3.y, 0.0f);
                    __half2 p0 = __floats2half2_rn(f0.x, f0.y);
                    __half2 p1 = __floats2half2_rn(f1.x, f1.y);
                    __half2 p2 = __floats2half2_rn(f2.x, f2.y);
                    __half2 p3 = __floats2half2_rn(f3.x, f3.y);
                    u.x = *(unsigned*)&p0; u.y = *(unsigned*)&p1;
                    u.z = *(unsigned*)&p2; u.w = *(unsigned*)&p3;
                    *(uint4*)&hout[row * 64 + (c >> 1)] = u;
                }
            }
            *(uint4*)&As[r * APAD + c] = u;

            float4 w0 = *(const float4*)&W[r * 128 + c];
            float4 w1 = *(const float4*)&W[r * 128 + c + 4];
            __half2 q0 = __floats2half2_rn(w0.x, w0.y);
            __half2 q1 = __floats2half2_rn(w0.z, w0.w);
            __half2 q2 = __floats2half2_rn(w1.x, w1.y);
            __half2 q3 = __floats2half2_rn(w1.z, w1.w);
            uint4 uw;
            uw.x = *(unsigned*)&q0; uw.y = *(unsigned*)&q1;
            uw.z = *(unsigned*)&q2; uw.w = *(unsigned*)&q3;
            *(uint4*)&Bs[r * APAD + c] = uw;
        }
    }
    __syncthreads();

    // ---- warp tiles: 4x2 warps, each 32(m) x 64(n) ----
    int wm = wid & 3;
    int wn = wid >> 2;
    float acc[2][8][4];
#pragma unroll
    for (int mt = 0; mt < 2; ++mt)
#pragma unroll
        for (int nt = 0; nt < 8; ++nt)
#pragma unroll
            for (int j = 0; j < 4; ++j) acc[mt][nt][j] = 0.0f;

    uint32_t As_base = smem_u32(As);
    uint32_t Bs_base = smem_u32(Bs);
    int a_row = wm * 32 + (lane & 7) + ((lane >> 3) & 1) * 8;
    int a_col = (lane >> 4) * 8;
    int b_row = (lane & 7) + ((lane >> 3) & 1) * 8;
    int b_col = wn * 64 + (lane >> 4) * 8;

#pragma unroll
    for (int kc = 0; kc < 8; ++kc) {
        int k0 = kc * 16;
        uint32_t afr[2][4];
#pragma unroll
        for (int mt = 0; mt < 2; ++mt) {
            uint32_t addr = As_base + (uint32_t)(((a_row + mt * 16) * APAD) + k0 + a_col) * 2u;
            ldsm_x4(afr[mt], addr);
        }
        uint32_t bfr[8][2];
#pragma unroll
        for (int j = 0; j < 4; ++j) {
            uint32_t r[4];
            uint32_t addr = Bs_base + (uint32_t)(((b_row + k0) * APAD) + b_col + j * 16) * 2u;
            ldsm_x4_t(r, addr);
            bfr[2 * j][0] = r[0]; bfr[2 * j][1] = r[1];
            bfr[2 * j + 1][0] = r[2]; bfr[2 * j + 1][1] = r[3];
        }
#pragma unroll
        for (int mt = 0; mt < 2; ++mt)
#pragma unroll
            for (int nt = 0; nt < 8; ++nt)
                mma16816(acc[mt][nt], afr[mt], bfr[nt]);
    }

    // ---- epilogue: payload = dinv[row] * C, fp16 ----
#pragma unroll
    for (int mt = 0; mt < 2; ++mt) {
        int grow0 = rowBase + wm * 32 + mt * 16 + (lane >> 2);
        float d0 = (grow0 < N_NODES) ? g_dinv[grow0] : 0.0f;
        float d8 = (grow0 + 8 < N_NODES) ? g_dinv[grow0 + 8] : 0.0f;
#pragma unroll
        for (int nt = 0; nt < 8; ++nt) {
            int cidx = wn * 32 + nt * 4 + (lane & 3);
            if (grow0 < N_NODES) {
                __half2 p = __floats2half2_rn(d0 * acc[mt][nt][0], d0 * acc[mt][nt][1]);
                g_hW2[grow0 * 64 + cidx] = *(unsigned*)&p;
            }
            if (grow0 + 8 < N_NODES) {
                __half2 p = __floats2half2_rn(d8 * acc[mt][nt][2], d8 * acc[mt][nt][3]);
                g_hW2[(grow0 + 8) * 64 + cidx] = *(unsigned*)&p;
            }
        }
    }
}

// ---------------- aggregate (4 nodes/warp, MLP-4 gather) + fused BN stats ----------------
// z_i = dinv_i * (sum_e payload[src_e] + payload[i]) + b
__global__ __launch_bounds__(256) void agg_kernel(const float* __restrict__ b, int layer) {
    __shared__ float ss[8][HID];
    __shared__ float sq[8][HID];
    int w = (threadIdx.x >> 5);
    int lane = threadIdx.x & 31;
    int node0 = ((blockIdx.x * blockDim.x + threadIdx.x) >> 5) * NPWA;
    const uint2* hw = (const uint2*)g_hW2;
    float4 bb = ((const float4*)b)[lane];
    float4 statS = make_float4(0, 0, 0, 0);
    float4 statQ = make_float4(0, 0, 0, 0);
#pragma unroll 1
    for (int nn = 0; nn < NPWA; ++nn) {
        int node = node0 + nn;
        if (node >= N_NODES) break;
        float4 acc = make_float4(0, 0, 0, 0);
        int e0 = g_rowptr[node] + g_boff[node >> 8];
        int e1 = g_rowptr[node + 1] + g_boff[(node + 1) >> 8];
        int e = e0;
        int efull = e0 + ((e1 - e0) & ~3);
        for (; e < efull; e += 4) {
            int s0 = g_esrc[e];
            int s1 = g_esrc[e + 1];
            int s2 = g_esrc[e + 2];
            int s3 = g_esrc[e + 3];
            uint2 u0 = hw[s0 * 32 + lane];
            uint2 u1 = hw[s1 * 32 + lane];
            uint2 u2 = hw[s2 * 32 + lane];
            uint2 u3 = hw[s3 * 32 + lane];
            float2 f;
            f = h2f(u0.x); acc.x += f.x; acc.y += f.y;
            f = h2f(u0.y); acc.z += f.x; acc.w += f.y;
            f = h2f(u1.x); acc.x += f.x; acc.y += f.y;
            f = h2f(u1.y); acc.z += f.x; acc.w += f.y;
            f = h2f(u2.x); acc.x += f.x; acc.y += f.y;
            f = h2f(u2.y); acc.z += f.x; acc.w += f.y;
            f = h2f(u3.x); acc.x += f.x; acc.y += f.y;
            f = h2f(u3.y); acc.z += f.x; acc.w += f.y;
        }
        for (; e < e1; ++e) {
            int s = g_esrc[e];
            uint2 u = hw[s * 32 + lane];
            float2 f;
            f = h2f(u.x); acc.x += f.x; acc.y += f.y;
            f = h2f(u.y); acc.z += f.x; acc.w += f.y;
        }
        // self term + scale + bias
        {
            uint2 u = hw[node * 32 + lane];
            float2 f0 = h2f(u.x), f1 = h2f(u.y);
            acc.x += f0.x; acc.y += f0.y; acc.z += f1.x; acc.w += f1.y;
        }
        float di = g_dinv[node];
        acc.x = di * acc.x + bb.x;
        acc.y = di * acc.y + bb.y;
        acc.z = di * acc.z + bb.z;
        acc.w = di * acc.w + bb.w;
        __half2 za = __floats2half2_rn(acc.x, acc.y);
        __half2 zb = __floats2half2_rn(acc.z, acc.w);
        uint2 zo;
        zo.x = *(unsigned*)&za; zo.y = *(unsigned*)&zb;
        ((uint2*)g_z2)[node * 32 + lane] = zo;
        statS.x += acc.x; statS.y += acc.y; statS.z += acc.z; statS.w += acc.w;
        statQ.x += acc.x * acc.x; statQ.y += acc.y * acc.y;
        statQ.z += acc.z * acc.z; statQ.w += acc.w * acc.w;
    }
    *(float4*)&ss[w][lane * 4] = statS;
    *(float4*)&sq[w][lane * 4] = statQ;
    __syncthreads();
    int t = threadIdx.x;
    int arr = t >> 7;
    int c = t & 127;
    const float* base = (arr == 0) ? &ss[0][0] : &sq[0][0];
    float total = 0.0f;
#pragma unroll
    for (int ww = 0; ww < 8; ++ww) total += base[ww * HID + c];
    atomicAdd(&g_stats[layer * 2 * HID + arr * HID + c], total);
}

__device__ __forceinline__ void pool_flush(int g, int lane, float4 s, float4 m, int cnt) {
    int base = g * HID + lane * 4;
    atomicAdd(&g_psum[base + 0], s.x);
    atomicAdd(&g_psum[base + 1], s.y);
    atomicAdd(&g_psum[base + 2], s.z);
    atomicAdd(&g_psum[base + 3], s.w);
    atomicMax(&g_pmax[base + 0], __float_as_uint(m.x));
    atomicMax(&g_pmax[base + 1], __float_as_uint(m.y));
    atomicMax(&g_pmax[base + 2], __float_as_uint(m.z));
    atomicMax(&g_pmax[base + 3], __float_as_uint(m.w));
    if (lane == 0) atomicAdd(&g_pcnt[g], cnt);
}

// pool with fused layer-3 BN + residual + relu (BN from g_stats[2]); fp16 inputs
__global__ __launch_bounds__(256) void pool_kernel(const int* __restrict__ batch,
                                                   const float* __restrict__ gam,
                                                   const float* __restrict__ bet) {
    __shared__ __align__(16) float s_sc[HID];
    __shared__ __align__(16) float s_sh[HID];
    {
        int t = threadIdx.x;
        if (t < HID) {
            const float* st = &g_stats[2 * 2 * HID];
            const float invN = 1.0f / (float)N_NODES;
            float mu = st[t] * invN;
            float var = st[HID + t] * invN - mu * mu;
            float scv = gam[t] * rsqrtf(var + BN_EPS);
            s_sc[t] = scv;
            s_sh[t] = bet[t] - mu * scv;
        }
        __syncthreads();
    }
    const int NPW = 16;
    int warp = (blockIdx.x * blockDim.x + threadIdx.x) >> 5;
    int lane = threadIdx.x & 31;
    int n0 = warp * NPW;
    if (n0 >= N_NODES) return;
    int n1 = min(n0 + NPW, N_NODES);
    const uint2* z2 = (const uint2*)g_z2;
    const uint2* r2 = (const uint2*)g_h2;
    float4 sc = *(const float4*)&s_sc[lane * 4];
    float4 sh = *(const float4*)&s_sh[lane * 4];
    float4 sacc = make_float4(0, 0, 0, 0);
    float4 macc = make_float4(0, 0, 0, 0);
    int cur = batch[n0];
    int cnt = 0;
    for (int n = n0; n < n1; ++n) {
        int g = batch[n];
        if (g != cur) {
            pool_flush(cur, lane, sacc, macc, cnt);
            sacc = make_float4(0, 0, 0, 0);
            macc = make_float4(0, 0, 0, 0);
            cnt = 0; cur = g;
        }
        uint2 zu = z2[n * 32 + lane];
        uint2 ru = r2[n * 32 + lane];
        float2 z0 = h2f(zu.x), z1 = h2f(zu.y);
        float2 r0 = h2f(ru.x), r1 = h2f(ru.y);
        float4 v;
        v.x = fmaxf(z0.x * sc.x + sh.x + r0.x, 0.0f);
        v.y = fmaxf(z0.y * sc.y + sh.y + r0.y, 0.0f);
        v.z = fmaxf(z1.x * sc.z + sh.z + r1.x, 0.0f);
        v.w = fmaxf(z1.y * sc.w + sh.w + r1.y, 0.0f);
        sacc.x += v.x; sacc.y += v.y; sacc.z += v.z; sacc.w += v.w;
        macc.x = fmaxf(macc.x, v.x); macc.y = fmaxf(macc.y, v.y);
        macc.z = fmaxf(macc.z, v.z); macc.w = fmaxf(macc.w, v.w);
        ++cnt;
    }
    pool_flush(cur, lane, sacc, macc, cnt);
}

__global__ __launch_bounds__(64) void head_kernel(const float* __restrict__ Wh,
                                                  const float* __restrict__ bh,
                                                  float* __restrict__ out) {
    int g = blockIdx.x;
    int c = threadIdx.x;
    float cntf = (float)g_pcnt[g];
    float inv = 1.0f / fmaxf(cntf, 1.0f);
    float acc = bh[c];
    for (int k = 0; k < HID; ++k) {
        float s = g_psum[g * HID + k];
        float m = s * inv;
        float mx = __uint_as_float(g_pmax[g * HID + k]);
        acc += m * Wh[k * N_CLASSES + c]
             + s * Wh[(HID + k) * N_CLASSES + c]
             + mx * Wh[(2 * HID + k) * N_CLASSES + c];
    }
    out[g * N_CLASSES + c] = acc;
}

// ---------------- launch ----------------
extern "C" void kernel_launch(void* const* d_in, const int* in_sizes, int n_in,
                              void* d_out, int out_size) {
    const float* x    = (const float*)d_in[0];
    const int*   ei   = (const int*)d_in[1];
    const int*   src  = ei;
    const int*   dst  = ei + N_EDGES;
    const int*   batch = (const int*)d_in[2];
    const float* W1 = (const float*)d_in[3];
    const float* b1 = (const float*)d_in[4];
    const float* g1 = (const float*)d_in[5];
    const float* be1 = (const float*)d_in[6];
    const float* W2 = (const float*)d_in[7];
    const float* b2 = (const float*)d_in[8];
    const float* g2 = (const float*)d_in[9];
    const float* be2 = (const float*)d_in[10];
    const float* W3 = (const float*)d_in[11];
    const float* b3 = (const float*)d_in[12];
    const float* g3 = (const float*)d_in[13];
    const float* be3 = (const float*)d_in[14];
    const float* Wh = (const float*)d_in[15];
    const float* bh = (const float*)d_in[16];
    float* out = (float*)d_out;

    cudaFuncSetAttribute(mma_kernel, cudaFuncAttributeMaxDynamicSharedMemorySize,
                         SMEM_MMA_BYTES);

    const int TB = 256;
    const int edgeBlocks = (N_EDGES + TB - 1) / TB;
    const int aggBlocks = (N_NODES + 8 * NPWA - 1) / (8 * NPWA);
    const int poolWarps = (N_NODES + 15) / 16;
    const int poolBlocks = (poolWarps * 32 + TB - 1) / TB;

    zero_kernel<<<256, TB>>>();
    hist_kernel<<<edgeBlocks, TB>>>(dst);
    scanA_kernel<<<SCAN_NB, 256>>>();
    scanB_kernel<<<1, 512>>>();
    scatter_kernel<<<edgeBlocks, TB>>>(src, dst);

    // layer 1: A = x (raw fp32)
    mma_kernel<<<MMA_BLOCKS, 256, SMEM_MMA_BYTES>>>(x, W1, nullptr, nullptr, 0, 0);
    agg_kernel<<<aggBlocks, TB>>>(b1, 0);

    // layer 2: A = h1 = relu(bn1(z1)), h1 -> g_h1
    mma_kernel<<<MMA_BLOCKS, 256, SMEM_MMA_BYTES>>>(nullptr, W2, g1, be1, 0, 1);
    agg_kernel<<<aggBlocks, TB>>>(b2, 1);

    // layer 3: A = h2 = relu(bn2(z2) + h1), h2 -> g_h2
    mma_kernel<<<MMA_BLOCKS, 256, SMEM_MMA_BYTES>>>(nullptr, W3, g2, be2, 1, 2);
    agg_kernel<<<aggBlocks, TB>>>(b3, 2);

    // pool (fused bn3 + residual h2) + head
    pool_kernel<<<poolBlocks, TB>>>(batch, g3, be3);
    head_kernel<<<N_GRAPHS, N_CLASSES>>>(Wh, bh, out);
}

// round 11
// speedup vs baseline: 1.9521x; 1.0053x over previous
#include <cuda_runtime.h>
#include <cuda_fp16.h>
#include <cstdint>

#define N_NODES 100000
#define N_EDGES 1600000
#define HID 128
#define NH4 (HID/4)
#define N_GRAPHS 512
#define N_CLASSES 64
#define BN_EPS 1e-5f
#define SCAN_NB 391   // ceil(N_NODES/256)

#define TILE_M 128
#define MMA_BLOCKS ((N_NODES + TILE_M - 1) / TILE_M)   // 782
#define APAD 136                                        // halves per smem row
#define SMEM_MMA_BYTES (2 * 128 * APAD * 2)             // A + B fp16 tiles = 69632
#define NPWA 4                                          // nodes per warp in agg

// ---------------- scratch (device globals; allocation-free) ----------------
__device__ __align__(16) unsigned g_hW2[N_NODES * 64]; // payload = dinv*h@W, half2/u32
__device__ __align__(16) unsigned g_z2 [N_NODES * 64]; // pre-BN conv output, fp16
__device__ __align__(16) unsigned g_h1 [N_NODES * 64]; // h1, fp16
__device__ __align__(16) unsigned g_h2 [N_NODES * 64]; // h2, fp16
__device__ float g_dinv[N_NODES];
__device__ int   g_cnt[N_NODES];
__device__ int   g_rowptr[N_NODES + 1]; // intra-block partial prefix (+ g_boff[i>>8])
__device__ int   g_cursor[N_NODES];
__device__ int   g_bsum[SCAN_NB];
__device__ int   g_boff[SCAN_NB];
__device__ int   g_esrc[N_EDGES];       // CSR-sorted source node per edge
__device__ float g_stats[3 * 2 * HID];
__device__ float g_psum[N_GRAPHS * HID];
__device__ unsigned g_pmax[N_GRAPHS * HID];
__device__ int   g_pcnt[N_GRAPHS];

// ---------------- warp-MMA helpers ----------------
__device__ __forceinline__ uint32_t smem_u32(const void* p) {
    uint32_t a;
    asm("{ .reg .u64 t; cvta.to.shared.u64 t, %1; cvt.u32.u64 %0, t; }" : "=r"(a) : "l"(p));
    return a;
}
__device__ __forceinline__ void ldsm_x4(uint32_t* r, uint32_t addr) {
    asm volatile("ldmatrix.sync.aligned.m8n8.x4.shared.b16 {%0,%1,%2,%3}, [%4];"
                 : "=r"(r[0]), "=r"(r[1]), "=r"(r[2]), "=r"(r[3]) : "r"(addr));
}
__device__ __forceinline__ void ldsm_x4_t(uint32_t* r, uint32_t addr) {
    asm volatile("ldmatrix.sync.aligned.m8n8.x4.trans.shared.b16 {%0,%1,%2,%3}, [%4];"
                 : "=r"(r[0]), "=r"(r[1]), "=r"(r[2]), "=r"(r[3]) : "r"(addr));
}
__device__ __forceinline__ void mma16816(float* c, const uint32_t* a, const uint32_t* b) {
    asm volatile(
        "mma.sync.aligned.m16n8k16.row.col.f32.f16.f16.f32 "
        "{%0,%1,%2,%3}, {%4,%5,%6,%7}, {%8,%9}, {%0,%1,%2,%3};"
        : "+f"(c[0]), "+f"(c[1]), "+f"(c[2]), "+f"(c[3])
        : "r"(a[0]), "r"(a[1]), "r"(a[2]), "r"(a[3]), "r"(b[0]), "r"(b[1]));
}
__device__ __forceinline__ float2 h2f(unsigned u) {
    return __half22float2(*(__half2*)&u);
}
__device__ __forceinline__ __half2 u2h(unsigned u) { return *(__half2*)&u; }

// ---------------- setup kernels ----------------

__global__ __launch_bounds__(256) void zero_kernel() {
    int i = blockIdx.x * blockDim.x + threadIdx.x;
    int stride = gridDim.x * blockDim.x;
    for (int j = i; j < N_NODES; j += stride) { g_cnt[j] = 0; g_cursor[j] = 0; }
    for (int j = i; j < 3 * 2 * HID; j += stride) g_stats[j] = 0.0f;
    for (int j = i; j < N_GRAPHS * HID; j += stride) { g_psum[j] = 0.0f; g_pmax[j] = 0u; }
    for (int j = i; j < N_GRAPHS; j += stride) g_pcnt[j] = 0;
}

__global__ __launch_bounds__(256) void hist_kernel(const int* __restrict__ dst) {
    int e = blockIdx.x * blockDim.x + threadIdx.x;
    if (e < N_EDGES) atomicAdd(&g_cnt[dst[e]], 1);
}

// per-block partial scan of g_cnt -> g_rowptr, block totals -> g_bsum, dinv folded in
__global__ __launch_bounds__(256) void scanA_kernel() {
    int t = threadIdx.x, b = blockIdx.x;
    int i = b * 256 + t;
    int v = (i < N_NODES) ? g_cnt[i] : 0;
    if (i < N_NODES) g_dinv[i] = rsqrtf((float)v + 1.0f);
    int x = v;
#pragma unroll
    for (int o = 1; o < 32; o <<= 1) {
        int y = __shfl_up_sync(0xffffffffu, x, o);
        if ((t & 31) >= o) x += y;
    }
    __shared__ int wsum[8];
    if ((t & 31) == 31) wsum[t >> 5] = x;
    __syncthreads();
    if (t < 32) {
        int s = (t < 8) ? wsum[t] : 0;
#pragma unroll
        for (int o = 1; o < 8; o <<= 1) {
            int y = __shfl_up_sync(0xffffffffu, s, o);
            if (t >= o) s += y;
        }
        if (t < 8) wsum[t] = s;
    }
    __syncthreads();
    int warpoff = (t >= 32) ? wsum[(t >> 5) - 1] : 0;
    int incl = x + warpoff;
    if (i < N_NODES) g_rowptr[i] = incl - v;
    if (t == 255) g_bsum[b] = incl;
}

__global__ __launch_bounds__(512) void scanB_kernel() {
    __shared__ int sh[512];
    int t = threadIdx.x;
    int v = (t < SCAN_NB) ? g_bsum[t] : 0;
    sh[t] = v;
    __syncthreads();
    for (int o = 1; o < 512; o <<= 1) {
        int y = (t >= o) ? sh[t - o] : 0;
        __syncthreads();
        sh[t] += y;
        __syncthreads();
    }
    if (t < SCAN_NB) g_boff[t] = sh[t] - v;
    if (t == SCAN_NB - 1) g_rowptr[N_NODES] = v;
}

__global__ __launch_bounds__(256) void scatter_kernel(const int* __restrict__ src,
                                                      const int* __restrict__ dst) {
    int e = blockIdx.x * blockDim.x + threadIdx.x;
    if (e >= N_EDGES) return;
    int d = dst[e], s = src[e];
    int pos = g_rowptr[d] + g_boff[d >> 8] + atomicAdd(&g_cursor[d], 1);
    g_esrc[pos] = s;
}

// ---------------- HMMA GEMM: payload = dinv * (A @ W) -> g_hW2 (fp16) ----------------
// mode 0: A = Aext (x fp32). mode 1: A = relu(bn(g_z2)), h -> g_h1.
// mode 2: A = relu(bn(g_z2) + g_h1), h -> g_h2.
__global__ __launch_bounds__(256) void mma_kernel(const float* __restrict__ Aext,
                                                  const float* __restrict__ W,
                                                  const float* __restrict__ gam,
                                                  const float* __restrict__ bet,
                                                  int statIdx, int mode) {
    extern __shared__ __align__(16) __half smh[];
    __half* As = smh;                  // [128][APAD]
    __half* Bs = smh + 128 * APAD;     // [128][APAD]
    __shared__ __align__(16) float s_sc[HID];
    __shared__ __align__(16) float s_sh[HID];

    int tid = threadIdx.x;
    int lane = tid & 31, wid = tid >> 5;
    int rowBase = blockIdx.x * TILE_M;

    if (mode != 0) {
        if (tid < HID) {
            const float* st = &g_stats[statIdx * 2 * HID];
            const float invN = 1.0f / (float)N_NODES;
            float mu = st[tid] * invN;
            float var = st[HID + tid] * invN - mu * mu;
            float scv = gam[tid] * rsqrtf(var + BN_EPS);
            s_sc[tid] = scv;
            s_sh[tid] = bet[tid] - mu * scv;
        }
        __syncthreads();
    }

    // ---- stage A (fp16 path with BN fusion) and B = W ----
    {
        int r = tid >> 1;            // 0..127
        int hf = (tid & 1) * 64;     // half-row offset
        int row = rowBase + r;
        bool valid = row < N_NODES;
        unsigned* hout = (mode == 1) ? g_h1 : g_h2;
#pragma unroll
        for (int cc = 0; cc < 8; ++cc) {
            int c = hf + cc * 8;
            uint4 u = make_uint4(0, 0, 0, 0);
            if (valid) {
                if (mode == 0) {
                    float4 v0 = *(const float4*)&Aext[row * 128 + c];
                    float4 v1 = *(const float4*)&Aext[row * 128 + c + 4];
                    __half2 p0 = __floats2half2_rn(v0.x, v0.y);
                    __half2 p1 = __floats2half2_rn(v0.z, v0.w);
                    __half2 p2 = __floats2half2_rn(v1.x, v1.y);
                    __half2 p3 = __floats2half2_rn(v1.z, v1.w);
                    u.x = *(unsigned*)&p0; u.y = *(unsigned*)&p1;
                    u.z = *(unsigned*)&p2; u.w = *(unsigned*)&p3;
                } else {
                    uint4 zu = *(const uint4*)&g_z2[row * 64 + (c >> 1)];
                    float2 f0 = h2f(zu.x), f1 = h2f(zu.y), f2 = h2f(zu.z), f3 = h2f(zu.w);
                    float4 s0 = *(const float4*)&s_sc[c];
                    float4 s1 = *(const float4*)&s_sc[c + 4];
                    float4 h0 = *(const float4*)&s_sh[c];
                    float4 h1 = *(const float4*)&s_sh[c + 4];
                    f0.x = f0.x * s0.x + h0.x; f0.y = f0.y * s0.y + h0.y;
                    f1.x = f1.x * s0.z + h0.z; f1.y = f1.y * s0.w + h0.w;
                    f2.x = f2.x * s1.x + h1.x; f2.y = f2.y * s1.y + h1.y;
                    f3.x = f3.x * s1.z + h1.z; f3.y = f3.y * s1.w + h1.w;
                    if (mode == 2) {
                        uint4 ru = *(const uint4*)&g_h1[row * 64 + (c >> 1)];
                        float2 r0 = h2f(ru.x), r1 = h2f(ru.y), r2 = h2f(ru.z), r3 = h2f(ru.w);
                        f0.x += r0.x; f0.y += r0.y;
                        f1.x += r1.x; f1.y += r1.y;
                        f2.x += r2.x; f2.y += r2.y;
                        f3.x += r3.x; f3.y += r3.y;
                    }
                    f0.x = fmaxf(f0.x, 0.0f); f0.y = fmaxf(f0.y, 0.0f);
                    f1.x = fmaxf(f1.x, 0.0f); f1.y = fmaxf(f1.y, 0.0f);
                    f2.x = fmaxf(f2.x, 0.0f); f2.y = fmaxf(f2.y, 0.0f);
                    f3.x = fmaxf(f3.x, 0.0f); f3.y = fmaxf(f3.y, 0.0f);
                    __half2 p0 = __floats2half2_rn(f0.x, f0.y);
                    __half2 p1 = __floats2half2_rn(f1.x, f1.y);
                    __half2 p2 = __floats2half2_rn(f2.x, f2.y);
                    __half2 p3 = __floats2half2_rn(f3.x, f3.y);
                    u.x = *(unsigned*)&p0; u.y = *(unsigned*)&p1;
                    u.z = *(unsigned*)&p2; u.w = *(unsigned*)&p3;
                    *(uint4*)&hout[row * 64 + (c >> 1)] = u;
                }
            }
            *(uint4*)&As[r * APAD + c] = u;

            float4 w0 = *(const float4*)&W[r * 128 + c];
            float4 w1 = *(const float4*)&W[r * 128 + c + 4];
            __half2 q0 = __floats2half2_rn(w0.x, w0.y);
            __half2 q1 = __floats2half2_rn(w0.z, w0.w);
            __half2 q2 = __floats2half2_rn(w1.x, w1.y);
            __half2 q3 = __floats2half2_rn(w1.z, w1.w);
            uint4 uw;
            uw.x = *(unsigned*)&q0; uw.y = *(unsigned*)&q1;
            uw.z = *(unsigned*)&q2; uw.w = *(unsigned*)&q3;
            *(uint4*)&Bs[r * APAD + c] = uw;
        }
    }
    __syncthreads();

    // ---- warp tiles: 4x2 warps, each 32(m) x 64(n) ----
    int wm = wid & 3;
    int wn = wid >> 2;
    float acc[2][8][4];
#pragma unroll
    for (int mt = 0; mt < 2; ++mt)
#pragma unroll
        for (int nt = 0; nt < 8; ++nt)
#pragma unroll
            for (int j = 0; j < 4; ++j) acc[mt][nt][j] = 0.0f;

    uint32_t As_base = smem_u32(As);
    uint32_t Bs_base = smem_u32(Bs);
    int a_row = wm * 32 + (lane & 7) + ((lane >> 3) & 1) * 8;
    int a_col = (lane >> 4) * 8;
    int b_row = (lane & 7) + ((lane >> 3) & 1) * 8;
    int b_col = wn * 64 + (lane >> 4) * 8;

#pragma unroll
    for (int kc = 0; kc < 8; ++kc) {
        int k0 = kc * 16;
        uint32_t afr[2][4];
#pragma unroll
        for (int mt = 0; mt < 2; ++mt) {
            uint32_t addr = As_base + (uint32_t)(((a_row + mt * 16) * APAD) + k0 + a_col) * 2u;
            ldsm_x4(afr[mt], addr);
        }
        uint32_t bfr[8][2];
#pragma unroll
        for (int j = 0; j < 4; ++j) {
            uint32_t r[4];
            uint32_t addr = Bs_base + (uint32_t)(((b_row + k0) * APAD) + b_col + j * 16) * 2u;
            ldsm_x4_t(r, addr);
            bfr[2 * j][0] = r[0]; bfr[2 * j][1] = r[1];
            bfr[2 * j + 1][0] = r[2]; bfr[2 * j + 1][1] = r[3];
        }
#pragma unroll
        for (int mt = 0; mt < 2; ++mt)
#pragma unroll
            for (int nt = 0; nt < 8; ++nt)
                mma16816(acc[mt][nt], afr[mt], bfr[nt]);
    }

    // ---- epilogue: payload = dinv[row] * C, fp16 ----
#pragma unroll
    for (int mt = 0; mt < 2; ++mt) {
        int grow0 = rowBase + wm * 32 + mt * 16 + (lane >> 2);
        float d0 = (grow0 < N_NODES) ? g_dinv[grow0] : 0.0f;
        float d8 = (grow0 + 8 < N_NODES) ? g_dinv[grow0 + 8] : 0.0f;
#pragma unroll
        for (int nt = 0; nt < 8; ++nt) {
            int cidx = wn * 32 + nt * 4 + (lane & 3);
            if (grow0 < N_NODES) {
                __half2 p = __floats2half2_rn(d0 * acc[mt][nt][0], d0 * acc[mt][nt][1]);
                g_hW2[grow0 * 64 + cidx] = *(unsigned*)&p;
            }
            if (grow0 + 8 < N_NODES) {
                __half2 p = __floats2half2_rn(d8 * acc[mt][nt][2], d8 * acc[mt][nt][3]);
                g_hW2[(grow0 + 8) * 64 + cidx] = *(unsigned*)&p;
            }
        }
    }
}

// ---------------- aggregate (4 nodes/warp, fp16-tree gather) + fused BN stats ----------------
// z_i = dinv_i * (sum_e payload[src_e] + payload[i]) + b
__global__ __launch_bounds__(256) void agg_kernel(const float* __restrict__ b, int layer) {
    __shared__ float ss[8][HID];
    __shared__ float sq[8][HID];
    int w = (threadIdx.x >> 5);
    int lane = threadIdx.x & 31;
    int node0 = ((blockIdx.x * blockDim.x + threadIdx.x) >> 5) * NPWA;
    const uint2* hw = (const uint2*)g_hW2;
    float4 bb = ((const float4*)b)[lane];
    float4 statS = make_float4(0, 0, 0, 0);
    float4 statQ = make_float4(0, 0, 0, 0);
#pragma unroll 1
    for (int nn = 0; nn < NPWA; ++nn) {
        int node = node0 + nn;
        if (node >= N_NODES) break;
        float4 acc = make_float4(0, 0, 0, 0);
        int e0 = g_rowptr[node] + g_boff[node >> 8];
        int e1 = g_rowptr[node + 1] + g_boff[(node + 1) >> 8];
        int e = e0;
        int efull = e0 + ((e1 - e0) & ~3);
        for (; e < efull; e += 4) {
            int s0 = g_esrc[e];
            int s1 = g_esrc[e + 1];
            int s2 = g_esrc[e + 2];
            int s3 = g_esrc[e + 3];
            uint2 u0 = hw[s0 * 32 + lane];
            uint2 u1 = hw[s1 * 32 + lane];
            uint2 u2 = hw[s2 * 32 + lane];
            uint2 u3 = hw[s3 * 32 + lane];
            // fp16 tree reduction per column, single convert per batch
            __half2 xs = __hadd2(__hadd2(u2h(u0.x), u2h(u1.x)),
                                 __hadd2(u2h(u2.x), u2h(u3.x)));
            __half2 ys = __hadd2(__hadd2(u2h(u0.y), u2h(u1.y)),
                                 __hadd2(u2h(u2.y), u2h(u3.y)));
            float2 fx = __half22float2(xs);
            float2 fy = __half22float2(ys);
            acc.x += fx.x; acc.y += fx.y;
            acc.z += fy.x; acc.w += fy.y;
        }
        for (; e < e1; ++e) {
            int s = g_esrc[e];
            uint2 u = hw[s * 32 + lane];
            float2 f;
            f = h2f(u.x); acc.x += f.x; acc.y += f.y;
            f = h2f(u.y); acc.z += f.x; acc.w += f.y;
        }
        // self term + scale + bias
        {
            uint2 u = hw[node * 32 + lane];
            float2 f0 = h2f(u.x), f1 = h2f(u.y);
            acc.x += f0.x; acc.y += f0.y; acc.z += f1.x; acc.w += f1.y;
        }
        float di = g_dinv[node];
        acc.x = di * acc.x + bb.x;
        acc.y = di * acc.y + bb.y;
        acc.z = di * acc.z + bb.z;
        acc.w = di * acc.w + bb.w;
        __half2 za = __floats2half2_rn(acc.x, acc.y);
        __half2 zb = __floats2half2_rn(acc.z, acc.w);
        uint2 zo;
        zo.x = *(unsigned*)&za; zo.y = *(unsigned*)&zb;
        ((uint2*)g_z2)[node * 32 + lane] = zo;
        statS.x += acc.x; statS.y += acc.y; statS.z += acc.z; statS.w += acc.w;
        statQ.x += acc.x * acc.x; statQ.y += acc.y * acc.y;
        statQ.z += acc.z * acc.z; statQ.w += acc.w * acc.w;
    }
    *(float4*)&ss[w][lane * 4] = statS;
    *(float4*)&sq[w][lane * 4] = statQ;
    __syncthreads();
    int t = threadIdx.x;
    int arr = t >> 7;
    int c = t & 127;
    const float* base = (arr == 0) ? &ss[0][0] : &sq[0][0];
    float total = 0.0f;
#pragma unroll
    for (int ww = 0; ww < 8; ++ww) total += base[ww * HID + c];
    atomicAdd(&g_stats[layer * 2 * HID + arr * HID + c], total);
}

__device__ __forceinline__ void pool_flush(int g, int lane, float4 s, float4 m, int cnt) {
    int base = g * HID + lane * 4;
    atomicAdd(&g_psum[base + 0], s.x);
    atomicAdd(&g_psum[base + 1], s.y);
    atomicAdd(&g_psum[base + 2], s.z);
    atomicAdd(&g_psum[base + 3], s.w);
    atomicMax(&g_pmax[base + 0], __float_as_uint(m.x));
    atomicMax(&g_pmax[base + 1], __float_as_uint(m.y));
    atomicMax(&g_pmax[base + 2], __float_as_uint(m.z));
    atomicMax(&g_pmax[base + 3], __float_as_uint(m.w));
    if (lane == 0) atomicAdd(&g_pcnt[g], cnt);
}

// pool with fused layer-3 BN + residual + relu (BN from g_stats[2]); fp16 inputs
__global__ __launch_bounds__(256) void pool_kernel(const int* __restrict__ batch,
                                                   const float* __restrict__ gam,
                                                   const float* __restrict__ bet) {
    __shared__ __align__(16) float s_sc[HID];
    __shared__ __align__(16) float s_sh[HID];
    {
        int t = threadIdx.x;
        if (t < HID) {
            const float* st = &g_stats[2 * 2 * HID];
            const float invN = 1.0f / (float)N_NODES;
            float mu = st[t] * invN;
            float var = st[HID + t] * invN - mu * mu;
            float scv = gam[t] * rsqrtf(var + BN_EPS);
            s_sc[t] = scv;
            s_sh[t] = bet[t] - mu * scv;
        }
        __syncthreads();
    }
    const int NPW = 16;
    int warp = (blockIdx.x * blockDim.x + threadIdx.x) >> 5;
    int lane = threadIdx.x & 31;
    int n0 = warp * NPW;
    if (n0 >= N_NODES) return;
    int n1 = min(n0 + NPW, N_NODES);
    const uint2* z2 = (const uint2*)g_z2;
    const uint2* r2 = (const uint2*)g_h2;
    float4 sc = *(const float4*)&s_sc[lane * 4];
    float4 sh = *(const float4*)&s_sh[lane * 4];
    float4 sacc = make_float4(0, 0, 0, 0);
    float4 macc = make_float4(0, 0, 0, 0);
    int cur = batch[n0];
    int cnt = 0;
    for (int n = n0; n < n1; ++n) {
        int g = batch[n];
        if (g != cur) {
            pool_flush(cur, lane, sacc, macc, cnt);
            sacc = make_float4(0, 0, 0, 0);
            macc = make_float4(0, 0, 0, 0);
            cnt = 0; cur = g;
        }
        uint2 zu = z2[n * 32 + lane];
        uint2 ru = r2[n * 32 + lane];
        float2 z0 = h2f(zu.x), z1 = h2f(zu.y);
        float2 r0 = h2f(ru.x), r1 = h2f(ru.y);
        float4 v;
        v.x = fmaxf(z0.x * sc.x + sh.x + r0.x, 0.0f);
        v.y = fmaxf(z0.y * sc.y + sh.y + r0.y, 0.0f);
        v.z = fmaxf(z1.x * sc.z + sh.z + r1.x, 0.0f);
        v.w = fmaxf(z1.y * sc.w + sh.w + r1.y, 0.0f);
        sacc.x += v.x; sacc.y += v.y; sacc.z += v.z; sacc.w += v.w;
        macc.x = fmaxf(macc.x, v.x); macc.y = fmaxf(macc.y, v.y);
        macc.z = fmaxf(macc.z, v.z); macc.w = fmaxf(macc.w, v.w);
        ++cnt;
    }
    pool_flush(cur, lane, sacc, macc, cnt);
}

__global__ __launch_bounds__(64) void head_kernel(const float* __restrict__ Wh,
                                                  const float* __restrict__ bh,
                                                  float* __restrict__ out) {
    int g = blockIdx.x;
    int c = threadIdx.x;
    float cntf = (float)g_pcnt[g];
    float inv = 1.0f / fmaxf(cntf, 1.0f);
    float acc = bh[c];
    for (int k = 0; k < HID; ++k) {
        float s = g_psum[g * HID + k];
        float m = s * inv;
        float mx = __uint_as_float(g_pmax[g * HID + k]);
        acc += m * Wh[k * N_CLASSES + c]
             + s * Wh[(HID + k) * N_CLASSES + c]
             + mx * Wh[(2 * HID + k) * N_CLASSES + c];
    }
    out[g * N_CLASSES + c] = acc;
}

// ---------------- launch ----------------
extern "C" void kernel_launch(void* const* d_in, const int* in_sizes, int n_in,
                              void* d_out, int out_size) {
    const float* x    = (const float*)d_in[0];
    const int*   ei   = (const int*)d_in[1];
    const int*   src  = ei;
    const int*   dst  = ei + N_EDGES;
    const int*   batch = (const int*)d_in[2];
    const float* W1 = (const float*)d_in[3];
    const float* b1 = (const float*)d_in[4];
    const float* g1 = (const float*)d_in[5];
    const float* be1 = (const float*)d_in[6];
    const float* W2 = (const float*)d_in[7];
    const float* b2 = (const float*)d_in[8];
    const float* g2 = (const float*)d_in[9];
    const float* be2 = (const float*)d_in[10];
    const float* W3 = (const float*)d_in[11];
    const float* b3 = (const float*)d_in[12];
    const float* g3 = (const float*)d_in[13];
    const float* be3 = (const float*)d_in[14];
    const float* Wh = (const float*)d_in[15];
    const float* bh = (const float*)d_in[16];
    float* out = (float*)d_out;

    cudaFuncSetAttribute(mma_kernel, cudaFuncAttributeMaxDynamicSharedMemorySize,
                         SMEM_MMA_BYTES);

    const int TB = 256;
    const int edgeBlocks = (N_EDGES + TB - 1) / TB;
    const int aggBlocks = (N_NODES + 8 * NPWA - 1) / (8 * NPWA);
    const int poolWarps = (N_NODES + 15) / 16;
    const int poolBlocks = (poolWarps * 32 + TB - 1) / TB;

    zero_kernel<<<256, TB>>>();
    hist_kernel<<<edgeBlocks, TB>>>(dst);
    scanA_kernel<<<SCAN_NB, 256>>>();
    scanB_kernel<<<1, 512>>>();
    scatter_kernel<<<edgeBlocks, TB>>>(src, dst);

    // layer 1: A = x (raw fp32)
    mma_kernel<<<MMA_BLOCKS, 256, SMEM_MMA_BYTES>>>(x, W1, nullptr, nullptr, 0, 0);
    agg_kernel<<<aggBlocks, TB>>>(b1, 0);

    // layer 2: A = h1 = relu(bn1(z1)), h1 -> g_h1
    mma_kernel<<<MMA_BLOCKS, 256, SMEM_MMA_BYTES>>>(nullptr, W2, g1, be1, 0, 1);
    agg_kernel<<<aggBlocks, TB>>>(b2, 1);

    // layer 3: A = h2 = relu(bn2(z2) + h1), h2 -> g_h2
    mma_kernel<<<MMA_BLOCKS, 256, SMEM_MMA_BYTES>>>(nullptr, W3, g2, be2, 1, 2);
    agg_kernel<<<aggBlocks, TB>>>(b3, 2);

    // pool (fused bn3 + residual h2) + head
    pool_kernel<<<poolBlocks, TB>>>(batch, g3, be3);
    head_kernel<<<N_GRAPHS, N_CLASSES>>>(Wh, bh, out);
}